// round 13
// baseline (speedup 1.0000x reference)
#include <cuda_runtime.h>
#include <cuda_bf16.h>
#include <math.h>
#include <stdint.h>

#define BB 4
#define NN 1024
#define DD 768
#define HH 12
#define CC 3072
#define C2 1536
#define ROWS (BB*NN)
#define KSEG 8

// ---------------- fp32 scratch ----------------
__device__ float g_xa[ROWS*DD];
__device__ float g_CT[128*NN];
__device__ float g_csum[65];
__device__ float g_R65p[KSEG*BB*128*DD];
__device__ float g_R65[BB*128*DD];
__device__ float g_wvt[2*DD*DD];
__device__ float g_vsum[2*BB*DD];
__device__ float g_w[2*HH];
__device__ float g_attn[BB*DD];
__device__ float g_bb[BB*DD];
__device__ float g_h[ROWS*CC];
__device__ float g_xgln[ROWS*C2];

// ---------------- bf16 hi/lo split buffers ----------------
__device__ __align__(16) __nv_bfloat16 g_xmh[ROWS*DD], g_xml[ROWS*DD];
__device__ __align__(16) __nv_bfloat16 g_w1h[CC*DD],   g_w1l[CC*DD];
__device__ __align__(16) __nv_bfloat16 g_w2h[DD*C2],   g_w2l[DD*C2];
__device__ __align__(16) __nv_bfloat16 g_wch[DD*C2],   g_wcl[DD*C2];   // [N=768, K=1536] = [Wb' | Ws]
__device__ __align__(16) __nv_bfloat16 g_uh[ROWS*C2],  g_ul[ROWS*C2];
__device__ __align__(16) __nv_bfloat16 g_axh[ROWS*C2], g_axl[ROWS*C2]; // [m | x] wide A buffer

__device__ __forceinline__ float geluf(float v) {
    return 0.5f * v * (1.0f + erff(v * 0.7071067811865476f));
}
__device__ __forceinline__ void split_bf16(float v, __nv_bfloat16& h, __nv_bfloat16& l) {
    h = __float2bfloat16(v);
    l = __float2bfloat16(v - __bfloat162float(h));
}

// ================= mma.sync helpers ====
__device__ __forceinline__ void ldsm_x4(uint32_t& r0, uint32_t& r1, uint32_t& r2, uint32_t& r3, uint32_t a) {
    asm volatile("ldmatrix.sync.aligned.m8n8.x4.shared.b16 {%0,%1,%2,%3}, [%4];"
        : "=r"(r0), "=r"(r1), "=r"(r2), "=r"(r3) : "r"(a));
}
__device__ __forceinline__ void mma_bf16(float* d, const uint32_t* a, const uint32_t* b) {
    asm volatile("mma.sync.aligned.m16n8k16.row.col.f32.bf16.bf16.f32 "
        "{%0,%1,%2,%3}, {%4,%5,%6,%7}, {%8,%9}, {%0,%1,%2,%3};"
        : "+f"(d[0]), "+f"(d[1]), "+f"(d[2]), "+f"(d[3])
        : "r"(a[0]), "r"(a[1]), "r"(a[2]), "r"(a[3]), "r"(b[0]), "r"(b[1]));
}
__device__ __forceinline__ void cp16(uint32_t s, const void* g) {
    asm volatile("cp.async.cg.shared.global [%0], [%1], 16;" :: "r"(s), "l"(g));
}
#define CP_COMMIT() asm volatile("cp.async.commit_group;" ::: "memory")
#define CP_WAIT1()  asm volatile("cp.async.wait_group 1;" ::: "memory")

// ================= split-bf16 GEMM: D = A @ B^T (3-phase over K) =============
// A: [M,K] K-major bf16 hi/lo.  B: [N,K] K-major bf16 hi/lo.
// Tile 128x128, K chunk 32, 256 thr, 3-stage cp.async ring, ONE sync/iter.
// modes: 1: C = gelu(v+bias)              (f32)
//        2: split(v+bias) -> Cbh/Cbl      (bf16 pair)
//        4: C = v + resid + bias2[(row>>10)*768 + col]
#define SROW 40                 // padded row stride in bf16 elems
#define TSZ (128*SROW)          // 5120 elems per tile
#define SMEM_DYN (3*2*TSZ*2)    // 61440 B: 3 stages x (A,B)
__global__ __launch_bounds__(256) void mma_gemm(
    const __nv_bfloat16* __restrict__ Ah, const __nv_bfloat16* __restrict__ Al,
    const __nv_bfloat16* __restrict__ Bh, const __nv_bfloat16* __restrict__ Bl,
    int K,
    float* __restrict__ C, int ldc,
    __nv_bfloat16* __restrict__ Cbh, __nv_bfloat16* __restrict__ Cbl, int ldcb,
    const float* __restrict__ bias, const float* __restrict__ bias2,
    const float* __restrict__ resid, int ldr, int mode)
{
    extern __shared__ __align__(16) __nv_bfloat16 sm[];
    const int tid = threadIdx.x, lane = tid & 31, wid = tid >> 5;
    const int m0 = blockIdx.y * 128, n0 = blockIdx.x * 128;
    const int wm = wid >> 1, wn = wid & 1;            // 4x2 warp grid
    const int mb = wm * 32, nb = wn * 64;

    float acc[2][8][4];
    #pragma unroll
    for (int i = 0; i < 2; i++)
        #pragma unroll
        for (int j = 0; j < 8; j++)
            #pragma unroll
            for (int q = 0; q < 4; q++) acc[i][j][q] = 0.0f;

    const int kSteps = K >> 5, nIter = 3 * kSteps;
    const int lr = tid >> 2, lc = (tid & 3) * 8;      // cp.async mapping
    const uint32_t sbase = (uint32_t)__cvta_generic_to_shared(sm);

    auto loadStage = [&](int iter, int st) {
        int ph = iter / kSteps, kc = iter - ph * kSteps;
        const __nv_bfloat16* A = (ph < 2) ? Ah : Al;
        const __nv_bfloat16* B = (ph == 1) ? Bl : Bh;
        int k0 = kc << 5;
        uint32_t sa = sbase + (uint32_t)st * (2*TSZ*2) + (lr*SROW + lc)*2;
        uint32_t sb = sa + TSZ*2;
        const uint32_t half = (uint32_t)(64*SROW*2);
        cp16(sa,        A + (size_t)(m0 + lr)      * K + k0 + lc);
        cp16(sa + half, A + (size_t)(m0 + lr + 64) * K + k0 + lc);
        cp16(sb,        B + (size_t)(n0 + lr)      * K + k0 + lc);
        cp16(sb + half, B + (size_t)(n0 + lr + 64) * K + k0 + lc);
    };

    loadStage(0, 0);
    CP_COMMIT();
    loadStage(1, 1);
    CP_COMMIT();
    int cs = 0, ps = 2;   // compute slot, prefetch slot
    for (int i = 0; i < nIter; i++) {
        CP_WAIT1();
        __syncthreads();
        if (i + 2 < nIter) loadStage(i + 2, ps);
        CP_COMMIT();
        uint32_t sa = sbase + (uint32_t)cs * (2*TSZ*2);
        uint32_t sb = sa + TSZ*2;
        #pragma unroll
        for (int ks = 0; ks < 2; ks++) {
            int kl = ks * 16;
            uint32_t af[2][4];
            #pragma unroll
            for (int mt = 0; mt < 2; mt++) {
                int row = mb + mt*16 + (lane & 15);
                int ko  = kl + ((lane >> 4) << 3);
                ldsm_x4(af[mt][0], af[mt][1], af[mt][2], af[mt][3],
                        sa + (uint32_t)(row*SROW + ko)*2);
            }
            uint32_t bf[8][2];
            #pragma unroll
            for (int nt4 = 0; nt4 < 4; nt4++) {
                int nrow = nb + nt4*16 + (lane & 7) + ((lane >> 4) << 3);
                int ko   = kl + (((lane >> 3) & 1) << 3);
                uint32_t r0, r1, r2, r3;
                ldsm_x4(r0, r1, r2, r3, sb + (uint32_t)(nrow*SROW + ko)*2);
                bf[nt4*2][0] = r0; bf[nt4*2][1] = r1;
                bf[nt4*2+1][0] = r2; bf[nt4*2+1][1] = r3;
            }
            #pragma unroll
            for (int mt = 0; mt < 2; mt++)
                #pragma unroll
                for (int nt = 0; nt < 8; nt++)
                    mma_bf16(acc[mt][nt], af[mt], bf[nt]);
        }
        cs = (cs == 2) ? 0 : cs + 1;
        ps = (ps == 2) ? 0 : ps + 1;
    }

    // epilogue
    #pragma unroll
    for (int mt = 0; mt < 2; mt++) {
        #pragma unroll
        for (int nt = 0; nt < 8; nt++) {
            int row = m0 + mb + mt*16 + (lane >> 2);
            int col = n0 + nb + nt*8 + (lane & 3)*2;
            #pragma unroll
            for (int h = 0; h < 2; h++) {
                int rr = row + h*8;
                #pragma unroll
                for (int q = 0; q < 2; q++) {
                    int cc = col + q;
                    float v = acc[mt][nt][h*2 + q];
                    if (mode == 1) {
                        C[(size_t)rr*ldc + cc] = geluf(v + bias[cc]);
                    } else if (mode == 2) {
                        float o = v + bias[cc];
                        __nv_bfloat16 hh, ll; split_bf16(o, hh, ll);
                        Cbh[(size_t)rr*ldcb + cc] = hh;
                        Cbl[(size_t)rr*ldcb + cc] = ll;
                    } else {
                        C[(size_t)rr*ldc + cc] = v + resid[(size_t)rr*ldr + cc]
                                               + bias2[(size_t)(rr >> 10)*DD + cc];
                    }
                }
            }
        }
    }
}

// ================= weight prep =================
__global__ void wsplit_kernel(const float* __restrict__ W,
                              __nv_bfloat16* __restrict__ Wh, __nv_bfloat16* __restrict__ Wl,
                              int K, int N) {
    __shared__ float t[32][33];
    int n0 = blockIdx.x * 32, k0 = blockIdx.y * 32;
    int tx = threadIdx.x, ty = threadIdx.y;
    for (int i = ty; i < 32; i += 8) t[i][tx] = W[(size_t)(k0 + i) * N + n0 + tx];
    __syncthreads();
    for (int i = ty; i < 32; i += 8) {
        float v = t[tx][i];
        __nv_bfloat16 h, l; split_bf16(v, h, l);
        Wh[(size_t)(n0 + i) * K + k0 + tx] = h;
        Wl[(size_t)(n0 + i) * K + k0 + tx] = l;
    }
}

// Ws = Wout[0:768]+Wout[768:1536] -> cols 768..1535 of concat B [768,1536]
__global__ void wsum_kernel(const float* __restrict__ Wout) {
    __shared__ float t[32][33];
    int n0 = blockIdx.x * 32, k0 = blockIdx.y * 32;
    int tx = threadIdx.x, ty = threadIdx.y;
    for (int i = ty; i < 32; i += 8)
        t[i][tx] = Wout[(size_t)(k0 + i) * DD + n0 + tx]
                 + Wout[(size_t)(DD + k0 + i) * DD + n0 + tx];
    __syncthreads();
    for (int i = ty; i < 32; i += 8) {
        float v = t[tx][i];
        __nv_bfloat16 h, l; split_bf16(v, h, l);
        g_wch[(size_t)(n0 + i) * C2 + DD + k0 + tx] = h;
        g_wcl[(size_t)(n0 + i) * C2 + DD + k0 + tx] = l;
    }
}

// Wb' = diag(ls2)*Wout[768:1536] -> cols 0..767 of concat B
__global__ void wscale_kernel(const float* __restrict__ Wout, const float* __restrict__ ls2) {
    __shared__ float t[32][33];
    int n0 = blockIdx.x * 32, k0 = blockIdx.y * 32;
    int tx = threadIdx.x, ty = threadIdx.y;
    for (int i = ty; i < 32; i += 8)
        t[i][tx] = ls2[k0 + i] * Wout[(size_t)(DD + k0 + i) * DD + n0 + tx];
    __syncthreads();
    for (int i = ty; i < 32; i += 8) {
        float v = t[tx][i];
        __nv_bfloat16 h, l; split_bf16(v, h, l);
        g_wch[(size_t)(n0 + i) * C2 + k0 + tx] = h;
        g_wcl[(size_t)(n0 + i) * C2 + k0 + tx] = l;
    }
}

__global__ void wvt_kernel(const float* __restrict__ Wqkv) {
    __shared__ float t[32][33];
    int p = blockIdx.z;
    const float* W = Wqkv + (size_t)p * DD * (3*DD) + 2*DD;
    int j0 = blockIdx.x * 32, k0 = blockIdx.y * 32;
    int tx = threadIdx.x, ty = threadIdx.y;
    for (int i = ty; i < 32; i += 8) t[i][tx] = W[(size_t)(k0 + i) * (3*DD) + j0 + tx];
    __syncthreads();
    for (int i = ty; i < 32; i += 8)
        g_wvt[(size_t)p * DD * DD + (size_t)(j0 + i) * DD + k0 + tx] = t[tx][i];
}

// ---------------- prep: rope coef table + reattn weights ----------------
__global__ void prep_kernel(const float* __restrict__ reattn,
                            const float* __restrict__ rng,
                            const float* __restrict__ rnb) {
    __shared__ float smix[24];
    int tid = threadIdx.x;
    float fi = (float)tid;
    float power = (fi - 512.0f) / 512.0f;
    #pragma unroll
    for (int t = 0; t < 16; t++) {
        float inv = powf(10000.0f, -(float)t / 16.0f);
        float fr = fi * inv;
        float c = cosf(fr), s = sinf(fr);
        int u1 = (2*t) & 15, u2 = (2*t+1) & 15;
        float sA = powf((2.0f*u1 + 12.8f) / 44.8f, -power);
        float sB = powf((2.0f*u2 + 12.8f) / 44.8f, -power);
        g_CT[(4*t+0)*NN + tid] = sA * c;
        g_CT[(4*t+1)*NN + tid] = sA * s;
        g_CT[(4*t+2)*NN + tid] = sB * c;
        g_CT[(4*t+3)*NN + tid] = sB * s;
    }
    g_CT[64*NN + tid] = 1.0f;
    __syncthreads();
    int warp = tid >> 5, lane = tid & 31;
    for (int c = warp; c < 65; c += 32) {
        float s = 0.0f;
        for (int q = lane; q < NN; q += 32) s += g_CT[c*NN + q];
        #pragma unroll
        for (int o = 16; o; o >>= 1) s += __shfl_down_sync(0xffffffffu, s, o);
        if (lane == 0) g_csum[c] = s;
    }
    if (tid < 24) {
        int p = tid / 12, g = tid % 12;
        float m = 0.0f;
        for (int h = 0; h < 12; h++) m += reattn[p*144 + h*12 + g];
        smix[tid] = m;
    }
    __syncthreads();
    if (tid < 24) {
        int p = tid / 12;
        float mean = 0.0f, var = 0.0f;
        for (int g = 0; g < 12; g++) mean += smix[p*12+g];
        mean *= (1.0f/12.0f);
        for (int g = 0; g < 12; g++) { float d = smix[p*12+g]-mean; var += d*d; }
        var *= (1.0f/12.0f);
        float rs = rsqrtf(var + 1e-5f);
        g_w[tid] = (smix[tid]-mean)*rs*rng[tid] + rnb[tid];
    }
}

// ---------------- LN of x -> xa (f32) and xm (bf16 hi/lo) ----------------
__global__ void ln_x_kernel(const float* __restrict__ x,
                            const float* __restrict__ g1, const float* __restrict__ b1,
                            const float* __restrict__ g2, const float* __restrict__ b2) {
    __shared__ float sh1[33], sh2[33];
    int row = blockIdx.x, tid = threadIdx.x;
    const float* xr = x + (size_t)row * DD;
    float s = 0.0f, s2 = 0.0f;
    #pragma unroll
    for (int c = tid; c < DD; c += 256) { float v = xr[c]; s += v; s2 += v*v; }
    int lane = tid & 31, warp = tid >> 5;
    #pragma unroll
    for (int o = 16; o; o >>= 1) { s += __shfl_down_sync(~0u, s, o); s2 += __shfl_down_sync(~0u, s2, o); }
    if (lane == 0) { sh1[warp] = s; sh2[warp] = s2; }
    __syncthreads();
    if (warp == 0) {
        s  = (lane < 8) ? sh1[lane] : 0.0f;
        s2 = (lane < 8) ? sh2[lane] : 0.0f;
        #pragma unroll
        for (int o = 4; o; o >>= 1) { s += __shfl_down_sync(~0u, s, o); s2 += __shfl_down_sync(~0u, s2, o); }
        if (lane == 0) { sh1[32] = s; sh2[32] = s2; }
    }
    __syncthreads();
    float mean = sh1[32] * (1.0f/DD);
    float var  = sh2[32] * (1.0f/DD) - mean*mean;
    float rs = rsqrtf(var + 1e-5f);
    #pragma unroll
    for (int c = tid; c < DD; c += 256) {
        float v = (xr[c] - mean) * rs;
        g_xa[(size_t)row*DD + c] = v * g1[c] + b1[c];
        float m = v * g2[c] + b2[c];
        __nv_bfloat16 h, l; split_bf16(m, h, l);
        g_xmh[(size_t)row*DD + c] = h;
        g_xml[(size_t)row*DD + c] = l;
    }
}

// ---------------- split of x -> cols 768..1535 of wide A ----------------
__global__ void xsplit_kernel(const float* __restrict__ x) {
    int c = blockIdx.x * 256 + threadIdx.x;
    int row = blockIdx.y;
    float v = x[(size_t)row*DD + c];
    __nv_bfloat16 h, l; split_bf16(v, h, l);
    g_axh[(size_t)row*C2 + DD + c] = h;
    g_axl[(size_t)row*C2 + DD + c] = l;
}

// ---------------- LN of gate half of h ----------------
__global__ void ln_g_kernel(const float* __restrict__ gg, const float* __restrict__ gb) {
    __shared__ float sh1[33], sh2[33];
    int row = blockIdx.x, tid = threadIdx.x;
    const float* xr = g_h + (size_t)row * CC + C2;
    float s = 0.0f, s2 = 0.0f;
    #pragma unroll
    for (int c = tid; c < C2; c += 256) { float v = xr[c]; s += v; s2 += v*v; }
    int lane = tid & 31, warp = tid >> 5;
    #pragma unroll
    for (int o = 16; o; o >>= 1) { s += __shfl_down_sync(~0u, s, o); s2 += __shfl_down_sync(~0u, s2, o); }
    if (lane == 0) { sh1[warp] = s; sh2[warp] = s2; }
    __syncthreads();
    if (warp == 0) {
        s  = (lane < 8) ? sh1[lane] : 0.0f;
        s2 = (lane < 8) ? sh2[lane] : 0.0f;
        #pragma unroll
        for (int o = 4; o; o >>= 1) { s += __shfl_down_sync(~0u, s, o); s2 += __shfl_down_sync(~0u, s2, o); }
        if (lane == 0) { sh1[32] = s; sh2[32] = s2; }
    }
    __syncthreads();
    float mean = sh1[32] * (1.0f/C2);
    float var  = sh2[32] * (1.0f/C2) - mean*mean;
    float rs = rsqrtf(var + 1e-5f);
    #pragma unroll
    for (int c = tid; c < C2; c += 256) {
        float v = (xr[c] - mean) * rs;
        g_xgln[(size_t)row*C2 + c] = v * gg[c] + gb[c];
    }
}

// ---------------- fp32 SGEMM, K-split into 8 segments (R65 reduction) ----------------
__global__ __launch_bounds__(256) void sgemm_part(
    const float* __restrict__ A, const float* __restrict__ B, float* __restrict__ Cp,
    int K, int ldb, int ldc, size_t bStride)
{
    __shared__ float As[8][128];
    __shared__ float Bs[8][128];
    int seg = blockIdx.y, bz = blockIdx.z;
    B += (size_t)bz * bStride;
    float* C = Cp + (size_t)seg * (BB*128*DD) + (size_t)bz * (128*DD);
    int kbase = seg * (K / KSEG);
    int tid = threadIdx.x;
    int n0 = blockIdx.x * 128;
    int aRow = tid >> 1, aCol = (tid & 1) * 4;
    int bRow = tid >> 5, bCol = (tid & 31) * 4;
    const float* Ag = A + (size_t)aRow * K + kbase + aCol;
    const float* Bg = B + (size_t)(kbase + bRow) * ldb + n0 + bCol;
    float acc[8][8];
    #pragma unroll
    for (int i = 0; i < 8; i++)
        #pragma unroll
        for (int j = 0; j < 8; j++) acc[i][j] = 0.0f;
    int ty = tid >> 4, tx = tid & 15;
    for (int k0 = 0; k0 < K / KSEG; k0 += 8) {
        float4 av = *(const float4*)(Ag + k0);
        As[aCol+0][aRow] = av.x; As[aCol+1][aRow] = av.y;
        As[aCol+2][aRow] = av.z; As[aCol+3][aRow] = av.w;
        float4 bv = *(const float4*)(Bg + (size_t)k0 * ldb);
        *(float4*)&Bs[bRow][bCol] = bv;
        __syncthreads();
        #pragma unroll
        for (int kk = 0; kk < 8; kk++) {
            float a[8], b[8];
            *(float4*)(a)   = *(const float4*)&As[kk][ty*8];
            *(float4*)(a+4) = *(const float4*)&As[kk][ty*8+4];
            *(float4*)(b)   = *(const float4*)&Bs[kk][tx*8];
            *(float4*)(b+4) = *(const float4*)&Bs[kk][tx*8+4];
            #pragma unroll
            for (int i = 0; i < 8; i++)
                #pragma unroll
                for (int j = 0; j < 8; j++)
                    acc[i][j] += a[i] * b[j];
        }
        __syncthreads();
    }
    #pragma unroll
    for (int i = 0; i < 8; i++) {
        int r = ty*8 + i;
        #pragma unroll
        for (int j = 0; j < 8; j++)
            C[(size_t)r*ldc + n0 + tx*8 + j] = acc[i][j];
    }
}

__global__ void r65red_kernel() {
    int idx = blockIdx.x * 256 + threadIdx.x;   // BB*128*DD total
    float s = 0.0f;
    #pragma unroll
    for (int seg = 0; seg < KSEG; seg++)
        s += g_R65p[(size_t)seg * (BB*128*DD) + idx];
    g_R65[idx] = s;
}

// ---------------- vsum: warp-per-output using transposed Wv ----------------
__global__ void vsum2_kernel(const float* __restrict__ bqkv) {
    int gw = (blockIdx.x * blockDim.x + threadIdx.x) >> 5;
    int lane = threadIdx.x & 31;
    int j = gw % DD;
    int b = (gw / DD) & 3;
    int p = gw / (4 * DD);
    const float* bv = bqkv + p * (3*DD) + 2*DD;
    const float* R  = g_R65 + (size_t)b * 128 * DD;
    const float* Wt = g_wvt + (size_t)p * DD * DD;
    int c = j & 63;
    float acc = 0.0f;
    if (c < 32) {
        int t = c >> 1;
        int r1, r2, j2; float sgn;
        if (!(c & 1)) { r1 = 4*t;   r2 = 4*t+1; j2 = j+1; sgn = -1.0f; }
        else          { r1 = 4*t+2; r2 = 4*t+3; j2 = j-1; sgn =  1.0f; }
        const float* R1 = R + (size_t)r1 * DD;
        const float* R2 = R + (size_t)r2 * DD;
        const float* Wa = Wt + (size_t)j  * DD;
        const float* Wb = Wt + (size_t)j2 * DD;
        float a1 = 0.0f, a2 = 0.0f;
        for (int k = lane; k < DD; k += 32) { a1 += Wa[k]*R1[k]; a2 += Wb[k]*R2[k]; }
        acc = a1 + sgn * a2;
        #pragma unroll
        for (int o = 16; o; o >>= 1) acc += __shfl_down_sync(~0u, acc, o);
        if (lane == 0) acc += bv[j]*g_csum[r1] + sgn*bv[j2]*g_csum[r2];
    } else {
        const float* Rr = R + (size_t)64 * DD;
        const float* Wa = Wt + (size_t)j * DD;
        float a = 0.0f;
        for (int k = lane; k < DD; k += 32) a += Wa[k]*Rr[k];
        #pragma unroll
        for (int o = 16; o; o >>= 1) a += __shfl_down_sync(~0u, a, o);
        if (lane == 0) acc = a + bv[j]*g_csum[64];
    }
    if (lane == 0) g_vsum[((size_t)p*BB + b)*DD + j] = acc;
}

// ---------------- attn vector (constant over sequence) ----------------
__global__ void attnvec_kernel(const float* __restrict__ Wproj, const float* __restrict__ bproj) {
    __shared__ float yv[2*DD];
    int b = blockIdx.x, tid = threadIdx.x;
    #pragma unroll
    for (int p = 0; p < 2; p++)
        yv[p*DD + tid] = g_w[p*HH + (tid >> 6)] * g_vsum[((size_t)p*BB + b)*DD + tid];
    __syncthreads();
    float acc = 0.0f;
    #pragma unroll
    for (int p = 0; p < 2; p++) {
        acc += bproj[p*DD + tid];
        const float* Wp = Wproj + (size_t)p * DD * DD;
        const float* y = yv + p*DD;
        for (int jj = 0; jj < DD; jj++)
            acc += y[jj] * Wp[(size_t)jj*DD + tid];
    }
    g_attn[(size_t)b*DD + tid] = acc;
}

// ---------------- bb[b][c] = bout[c] + sum_k ls1[k]*attn[b][k]*Wout[k][c] ----------------
__global__ void bb_kernel(const float* __restrict__ Wout, const float* __restrict__ bout,
                          const float* __restrict__ ls1) {
    __shared__ float cv[DD];
    int b = blockIdx.x, c = threadIdx.x;
    cv[c] = ls1[c] * g_attn[(size_t)b*DD + c];
    __syncthreads();
    float acc = bout[c];
    for (int k = 0; k < DD; k++)
        acc += cv[k] * Wout[(size_t)k*DD + c];
    g_bb[(size_t)b*DD + c] = acc;
}

// ---------------- tiled depthwise conv (K=21) + gate -> u bf16 hi/lo ----------------
__global__ __launch_bounds__(256) void conv_kernel(const float* __restrict__ cw,
                                                   const float* __restrict__ cb) {
    __shared__ float sx[84*64];
    __shared__ float scw[64*21];
    int ch0 = blockIdx.x * 64;
    int r0  = blockIdx.y * 64;
    int tid = threadIdx.x;
    for (int q = tid; q < 64*21; q += 256) {
        int ch = q / 21, k = q % 21;
        scw[ch*21 + k] = cw[(size_t)(ch0 + ch)*21 + k];
    }
    int b = r0 >> 10, i0 = r0 & 1023;
    for (int q = tid; q < 84*64; q += 256) {
        int rr = q >> 6, ch = q & 63;
        int ii = i0 - 10 + rr;
        sx[rr*64 + ch] = (ii >= 0 && ii < NN)
            ? g_xgln[((size_t)((b << 10) + ii))*C2 + ch0 + ch] : 0.0f;
    }
    __syncthreads();
    int ch = tid & 63, ty = tid >> 6;
    float cbv = cb[ch0 + ch];
    float w[21];
    #pragma unroll
    for (int k = 0; k < 21; k++) w[k] = scw[ch*21 + k];
    for (int rg = 0; rg < 16; rg++) {
        int r = ty*16 + rg;
        float acc = cbv;
        #pragma unroll
        for (int k = 0; k < 21; k++)
            acc += w[k] * sx[(r + k)*64 + ch];
        int row = r0 + r;
        float v = g_h[(size_t)row*CC + ch0 + ch] * acc;
        __nv_bfloat16 h, l; split_bf16(v, h, l);
        g_uh[(size_t)row*C2 + ch0 + ch] = h;
        g_ul[(size_t)row*C2 + ch0 + ch] = l;
    }
}

// ---------------- launch ----------------
extern "C" void kernel_launch(void* const* d_in, const int* in_sizes, int n_in,
                              void* d_out, int out_size) {
    const float* x      = (const float*)d_in[0];
    const float* Wqkv   = (const float*)d_in[1];
    const float* bqkv   = (const float*)d_in[2];
    const float* Wproj  = (const float*)d_in[3];
    const float* bproj  = (const float*)d_in[4];
    const float* reattn = (const float*)d_in[9];
    const float* rn_g   = (const float*)d_in[10];
    const float* rn_b   = (const float*)d_in[11];
    const float* ln1_g  = (const float*)d_in[12];
    const float* ln1_b  = (const float*)d_in[13];
    const float* ln2_g  = (const float*)d_in[14];
    const float* ln2_b  = (const float*)d_in[15];
    const float* ls1    = (const float*)d_in[16];
    const float* ls2    = (const float*)d_in[17];
    const float* W1     = (const float*)d_in[18];
    const float* b1     = (const float*)d_in[19];
    const float* gn_g   = (const float*)d_in[20];
    const float* gn_b   = (const float*)d_in[21];
    const float* conv_w = (const float*)d_in[22];
    const float* conv_b = (const float*)d_in[23];
    const float* W2     = (const float*)d_in[24];
    const float* b2     = (const float*)d_in[25];
    const float* Wout   = (const float*)d_in[26];
    const float* bout   = (const float*)d_in[27];
    float* out = (float*)d_out;

    cudaFuncSetAttribute(mma_gemm, cudaFuncAttributeMaxDynamicSharedMemorySize, SMEM_DYN);

    float *xa, *CT, *R65p, *hbuf, *bb;
    __nv_bfloat16 *xmh, *xml, *w1h, *w1l, *w2h, *w2l, *wch, *wcl;
    __nv_bfloat16 *uh, *ul, *axh, *axl;
    cudaGetSymbolAddress((void**)&xa,    g_xa);
    cudaGetSymbolAddress((void**)&CT,    g_CT);
    cudaGetSymbolAddress((void**)&R65p,  g_R65p);
    cudaGetSymbolAddress((void**)&hbuf,  g_h);
    cudaGetSymbolAddress((void**)&bb,    g_bb);
    cudaGetSymbolAddress((void**)&xmh,   g_xmh);  cudaGetSymbolAddress((void**)&xml, g_xml);
    cudaGetSymbolAddress((void**)&w1h,   g_w1h);  cudaGetSymbolAddress((void**)&w1l, g_w1l);
    cudaGetSymbolAddress((void**)&w2h,   g_w2h);  cudaGetSymbolAddress((void**)&w2l, g_w2l);
    cudaGetSymbolAddress((void**)&wch,   g_wch);  cudaGetSymbolAddress((void**)&wcl, g_wcl);
    cudaGetSymbolAddress((void**)&uh,    g_uh);   cudaGetSymbolAddress((void**)&ul,  g_ul);
    cudaGetSymbolAddress((void**)&axh,   g_axh);  cudaGetSymbolAddress((void**)&axl, g_axl);

    dim3 t32x8(32, 8);
    // weight prep
    prep_kernel<<<1, 1024>>>(reattn, rn_g, rn_b);
    wsplit_kernel<<<dim3(CC/32, DD/32), t32x8>>>(W1, w1h, w1l, DD, CC);
    wsplit_kernel<<<dim3(DD/32, C2/32), t32x8>>>(W2, w2h, w2l, C2, DD);
    wsum_kernel<<<dim3(DD/32, DD/32), t32x8>>>(Wout);
    wscale_kernel<<<dim3(DD/32, DD/32), t32x8>>>(Wout, ls2);
    wvt_kernel<<<dim3(DD/32, DD/32, 2), t32x8>>>(Wqkv);

    // LN + split of x into wide A cols 768..1535
    ln_x_kernel<<<ROWS, 256>>>(x, ln1_g, ln1_b, ln2_g, ln2_b);
    xsplit_kernel<<<dim3(3, ROWS), 256>>>(x);

    // attention path (exact fp32, constant over sequence)
    sgemm_part<<<dim3(6, KSEG, 4), 256>>>(CT, xa, R65p, NN, DD, DD, (size_t)NN*DD);
    r65red_kernel<<<(BB*128*DD)/256, 256>>>();
    vsum2_kernel<<<768, 256>>>(bqkv);
    attnvec_kernel<<<4, 768>>>(Wproj, bproj);
    bb_kernel<<<4, 768>>>(Wout, bout, ls1);

    // h = gelu(xm @ W1 + b1)
    mma_gemm<<<dim3(CC/128, ROWS/128), 256, SMEM_DYN>>>(
        xmh, xml, w1h, w1l, DD, hbuf, CC,
        nullptr, nullptr, 0, b1, nullptr, nullptr, 0, 1);
    ln_g_kernel<<<ROWS, 256>>>(gn_g, gn_b);
    conv_kernel<<<dim3(C2/64, ROWS/64), 256>>>(conv_w, conv_b);
    // m = u @ W2 + b2 -> bf16 split into wide A cols 0..767
    mma_gemm<<<dim3(DD/128, ROWS/128), 256, SMEM_DYN>>>(
        uh, ul, w2h, w2l, C2, nullptr, 0,
        axh, axl, C2, b2, nullptr, nullptr, 0, 2);
    // out = [m|x] @ [Wb'|Ws]^T + x + bb[batch]
    mma_gemm<<<dim3(DD/128, ROWS/128), 256, SMEM_DYN>>>(
        axh, axl, wch, wcl, C2, out, DD,
        nullptr, nullptr, 0, nullptr, bb, x, DD, 4);
}

// round 14
// speedup vs baseline: 1.0768x; 1.0768x over previous
#include <cuda_runtime.h>
#include <cuda_bf16.h>
#include <math.h>
#include <stdint.h>

#define BB 4
#define NN 1024
#define DD 768
#define HH 12
#define CC 3072
#define C2 1536
#define ROWS (BB*NN)
#define KSEG 8

// ---------------- fp32 scratch ----------------
__device__ float g_xa[ROWS*DD];
__device__ float g_CT[128*NN];
__device__ float g_csum[65];
__device__ float g_R65p[KSEG*BB*128*DD];
__device__ float g_R65[BB*128*DD];
__device__ float g_wvt[2*DD*DD];
__device__ float g_vsum[2*BB*DD];
__device__ float g_w[2*HH];
__device__ float g_attn[BB*DD];
__device__ float g_bb[BB*DD];
__device__ float g_h[ROWS*CC];
__device__ float g_xgln[ROWS*C2];

// ---------------- bf16 hi/lo split buffers ----------------
__device__ __align__(16) __nv_bfloat16 g_xmh[ROWS*DD], g_xml[ROWS*DD];
__device__ __align__(16) __nv_bfloat16 g_w1h[CC*DD],   g_w1l[CC*DD];
__device__ __align__(16) __nv_bfloat16 g_w2h[DD*C2],   g_w2l[DD*C2];
__device__ __align__(16) __nv_bfloat16 g_wch[DD*C2],   g_wcl[DD*C2];   // [N=768, K=1536] = [Wb' | Ws]
__device__ __align__(16) __nv_bfloat16 g_uh[ROWS*C2],  g_ul[ROWS*C2];
__device__ __align__(16) __nv_bfloat16 g_axh[ROWS*C2], g_axl[ROWS*C2]; // [m | x] wide A buffer

__device__ __forceinline__ float geluf(float v) {
    return 0.5f * v * (1.0f + erff(v * 0.7071067811865476f));
}
__device__ __forceinline__ void split_bf16(float v, __nv_bfloat16& h, __nv_bfloat16& l) {
    h = __float2bfloat16(v);
    l = __float2bfloat16(v - __bfloat162float(h));
}

// ================= mma.sync helpers ====
__device__ __forceinline__ void ldsm_x4(uint32_t& r0, uint32_t& r1, uint32_t& r2, uint32_t& r3, uint32_t a) {
    asm volatile("ldmatrix.sync.aligned.m8n8.x4.shared.b16 {%0,%1,%2,%3}, [%4];"
        : "=r"(r0), "=r"(r1), "=r"(r2), "=r"(r3) : "r"(a));
}
__device__ __forceinline__ void mma_bf16(float* d, const uint32_t* a, const uint32_t* b) {
    asm volatile("mma.sync.aligned.m16n8k16.row.col.f32.bf16.bf16.f32 "
        "{%0,%1,%2,%3}, {%4,%5,%6,%7}, {%8,%9}, {%0,%1,%2,%3};"
        : "+f"(d[0]), "+f"(d[1]), "+f"(d[2]), "+f"(d[3])
        : "r"(a[0]), "r"(a[1]), "r"(a[2]), "r"(a[3]), "r"(b[0]), "r"(b[1]));
}
__device__ __forceinline__ void cp16(uint32_t s, const void* g) {
    asm volatile("cp.async.cg.shared.global [%0], [%1], 16;" :: "r"(s), "l"(g));
}
#define CP_COMMIT() asm volatile("cp.async.commit_group;" ::: "memory")
#define CP_WAIT1()  asm volatile("cp.async.wait_group 1;" ::: "memory")

// ================= split-bf16 GEMM: D = A @ B^T (3-phase, round-11 engine) =============
// A: [M,K] K-major bf16 hi/lo.  B: [N,K] K-major bf16 hi/lo.
// Tile 128x128, K chunk 32, 256 thr, static double-buffered cp.async.
// 3 phases over K: Ah.Bh, Ah.Bl, Al.Bh accumulated in one fp32 acc.
// modes: 1: C = gelu(v+bias)              (f32)
//        2: split(v+bias) -> Cbh/Cbl      (bf16 pair)
//        4: C = v + resid + bias2[(row>>10)*768 + col]
#define SROW 40   // padded row stride in bf16 elems (80B: conflict-free ldmatrix)
__global__ __launch_bounds__(256) void mma_gemm(
    const __nv_bfloat16* __restrict__ Ah, const __nv_bfloat16* __restrict__ Al,
    const __nv_bfloat16* __restrict__ Bh, const __nv_bfloat16* __restrict__ Bl,
    int K,
    float* __restrict__ C, int ldc,
    __nv_bfloat16* __restrict__ Cbh, __nv_bfloat16* __restrict__ Cbl, int ldcb,
    const float* __restrict__ bias, const float* __restrict__ bias2,
    const float* __restrict__ resid, int ldr, int mode)
{
    __shared__ __align__(16) __nv_bfloat16 sA[2][128*SROW];
    __shared__ __align__(16) __nv_bfloat16 sB[2][128*SROW];
    const int tid = threadIdx.x, lane = tid & 31, wid = tid >> 5;
    const int m0 = blockIdx.y * 128, n0 = blockIdx.x * 128;
    const int wm = wid >> 1, wn = wid & 1;            // 4x2 warp grid
    const int mb = wm * 32, nb = wn * 64;

    float acc[2][8][4];
    #pragma unroll
    for (int i = 0; i < 2; i++)
        #pragma unroll
        for (int j = 0; j < 8; j++)
            #pragma unroll
            for (int q = 0; q < 4; q++) acc[i][j][q] = 0.0f;

    const int kSteps = K >> 5, nIter = 3 * kSteps;
    const int lr = tid >> 2, lc = (tid & 3) * 8;      // cp.async mapping

    auto loadStage = [&](int iter, int st) {
        int ph = iter / kSteps, kc = iter % kSteps;
        const __nv_bfloat16* A = (ph < 2) ? Ah : Al;
        const __nv_bfloat16* B = (ph == 1) ? Bl : Bh;
        int k0 = kc << 5;
        uint32_t sa = (uint32_t)__cvta_generic_to_shared(&sA[st][0]);
        uint32_t sb = (uint32_t)__cvta_generic_to_shared(&sB[st][0]);
        cp16(sa + (lr*SROW + lc)*2,        A + (size_t)(m0 + lr)      * K + k0 + lc);
        cp16(sa + ((lr+64)*SROW + lc)*2,   A + (size_t)(m0 + lr + 64) * K + k0 + lc);
        cp16(sb + (lr*SROW + lc)*2,        B + (size_t)(n0 + lr)      * K + k0 + lc);
        cp16(sb + ((lr+64)*SROW + lc)*2,   B + (size_t)(n0 + lr + 64) * K + k0 + lc);
    };

    loadStage(0, 0);
    CP_COMMIT();
    for (int i = 0; i < nIter; i++) {
        if (i + 1 < nIter) loadStage(i + 1, (i + 1) & 1);
        CP_COMMIT();
        CP_WAIT1();
        __syncthreads();
        int st = i & 1;
        uint32_t sa = (uint32_t)__cvta_generic_to_shared(&sA[st][0]);
        uint32_t sb = (uint32_t)__cvta_generic_to_shared(&sB[st][0]);
        #pragma unroll
        for (int ks = 0; ks < 2; ks++) {
            int kl = ks * 16;
            uint32_t af[2][4];
            #pragma unroll
            for (int mt = 0; mt < 2; mt++) {
                int row = mb + mt*16 + (lane & 15);
                int ko  = kl + ((lane >> 4) << 3);
                ldsm_x4(af[mt][0], af[mt][1], af[mt][2], af[mt][3],
                        sa + (uint32_t)(row*SROW + ko)*2);
            }
            uint32_t bf[8][2];
            #pragma unroll
            for (int nt4 = 0; nt4 < 4; nt4++) {
                int nrow = nb + nt4*16 + (lane & 7) + ((lane >> 4) << 3);
                int ko   = kl + (((lane >> 3) & 1) << 3);
                uint32_t r0, r1, r2, r3;
                ldsm_x4(r0, r1, r2, r3, sb + (uint32_t)(nrow*SROW + ko)*2);
                bf[nt4*2][0] = r0; bf[nt4*2][1] = r1;
                bf[nt4*2+1][0] = r2; bf[nt4*2+1][1] = r3;
            }
            #pragma unroll
            for (int mt = 0; mt < 2; mt++)
                #pragma unroll
                for (int nt = 0; nt < 8; nt++)
                    mma_bf16(acc[mt][nt], af[mt], bf[nt]);
        }
        __syncthreads();
    }

    // epilogue
    #pragma unroll
    for (int mt = 0; mt < 2; mt++) {
        #pragma unroll
        for (int nt = 0; nt < 8; nt++) {
            int row = m0 + mb + mt*16 + (lane >> 2);
            int col = n0 + nb + nt*8 + (lane & 3)*2;
            #pragma unroll
            for (int h = 0; h < 2; h++) {
                int rr = row + h*8;
                #pragma unroll
                for (int q = 0; q < 2; q++) {
                    int cc = col + q;
                    float v = acc[mt][nt][h*2 + q];
                    if (mode == 1) {
                        C[(size_t)rr*ldc + cc] = geluf(v + bias[cc]);
                    } else if (mode == 2) {
                        float o = v + bias[cc];
                        __nv_bfloat16 hh, ll; split_bf16(o, hh, ll);
                        Cbh[(size_t)rr*ldcb + cc] = hh;
                        Cbl[(size_t)rr*ldcb + cc] = ll;
                    } else {
                        C[(size_t)rr*ldc + cc] = v + resid[(size_t)rr*ldr + cc]
                                               + bias2[(size_t)(rr >> 10)*DD + cc];
                    }
                }
            }
        }
    }
}

// ================= weight prep =================
__global__ void wsplit_kernel(const float* __restrict__ W,
                              __nv_bfloat16* __restrict__ Wh, __nv_bfloat16* __restrict__ Wl,
                              int K, int N) {
    __shared__ float t[32][33];
    int n0 = blockIdx.x * 32, k0 = blockIdx.y * 32;
    int tx = threadIdx.x, ty = threadIdx.y;
    for (int i = ty; i < 32; i += 8) t[i][tx] = W[(size_t)(k0 + i) * N + n0 + tx];
    __syncthreads();
    for (int i = ty; i < 32; i += 8) {
        float v = t[tx][i];
        __nv_bfloat16 h, l; split_bf16(v, h, l);
        Wh[(size_t)(n0 + i) * K + k0 + tx] = h;
        Wl[(size_t)(n0 + i) * K + k0 + tx] = l;
    }
}

// Ws = Wout[0:768]+Wout[768:1536] -> cols 768..1535 of concat B [768,1536]
__global__ void wsum_kernel(const float* __restrict__ Wout) {
    __shared__ float t[32][33];
    int n0 = blockIdx.x * 32, k0 = blockIdx.y * 32;
    int tx = threadIdx.x, ty = threadIdx.y;
    for (int i = ty; i < 32; i += 8)
        t[i][tx] = Wout[(size_t)(k0 + i) * DD + n0 + tx]
                 + Wout[(size_t)(DD + k0 + i) * DD + n0 + tx];
    __syncthreads();
    for (int i = ty; i < 32; i += 8) {
        float v = t[tx][i];
        __nv_bfloat16 h, l; split_bf16(v, h, l);
        g_wch[(size_t)(n0 + i) * C2 + DD + k0 + tx] = h;
        g_wcl[(size_t)(n0 + i) * C2 + DD + k0 + tx] = l;
    }
}

// Wb' = diag(ls2)*Wout[768:1536] -> cols 0..767 of concat B
__global__ void wscale_kernel(const float* __restrict__ Wout, const float* __restrict__ ls2) {
    __shared__ float t[32][33];
    int n0 = blockIdx.x * 32, k0 = blockIdx.y * 32;
    int tx = threadIdx.x, ty = threadIdx.y;
    for (int i = ty; i < 32; i += 8)
        t[i][tx] = ls2[k0 + i] * Wout[(size_t)(DD + k0 + i) * DD + n0 + tx];
    __syncthreads();
    for (int i = ty; i < 32; i += 8) {
        float v = t[tx][i];
        __nv_bfloat16 h, l; split_bf16(v, h, l);
        g_wch[(size_t)(n0 + i) * C2 + k0 + tx] = h;
        g_wcl[(size_t)(n0 + i) * C2 + k0 + tx] = l;
    }
}

__global__ void wvt_kernel(const float* __restrict__ Wqkv) {
    __shared__ float t[32][33];
    int p = blockIdx.z;
    const float* W = Wqkv + (size_t)p * DD * (3*DD) + 2*DD;
    int j0 = blockIdx.x * 32, k0 = blockIdx.y * 32;
    int tx = threadIdx.x, ty = threadIdx.y;
    for (int i = ty; i < 32; i += 8) t[i][tx] = W[(size_t)(k0 + i) * (3*DD) + j0 + tx];
    __syncthreads();
    for (int i = ty; i < 32; i += 8)
        g_wvt[(size_t)p * DD * DD + (size_t)(j0 + i) * DD + k0 + tx] = t[tx][i];
}

// ---------------- prep: rope coef table + reattn weights ----------------
__global__ void prep_kernel(const float* __restrict__ reattn,
                            const float* __restrict__ rng,
                            const float* __restrict__ rnb) {
    __shared__ float smix[24];
    int tid = threadIdx.x;
    float fi = (float)tid;
    float power = (fi - 512.0f) / 512.0f;
    #pragma unroll
    for (int t = 0; t < 16; t++) {
        float inv = powf(10000.0f, -(float)t / 16.0f);
        float fr = fi * inv;
        float c = cosf(fr), s = sinf(fr);
        int u1 = (2*t) & 15, u2 = (2*t+1) & 15;
        float sA = powf((2.0f*u1 + 12.8f) / 44.8f, -power);
        float sB = powf((2.0f*u2 + 12.8f) / 44.8f, -power);
        g_CT[(4*t+0)*NN + tid] = sA * c;
        g_CT[(4*t+1)*NN + tid] = sA * s;
        g_CT[(4*t+2)*NN + tid] = sB * c;
        g_CT[(4*t+3)*NN + tid] = sB * s;
    }
    g_CT[64*NN + tid] = 1.0f;
    __syncthreads();
    int warp = tid >> 5, lane = tid & 31;
    for (int c = warp; c < 65; c += 32) {
        float s = 0.0f;
        for (int q = lane; q < NN; q += 32) s += g_CT[c*NN + q];
        #pragma unroll
        for (int o = 16; o; o >>= 1) s += __shfl_down_sync(0xffffffffu, s, o);
        if (lane == 0) g_csum[c] = s;
    }
    if (tid < 24) {
        int p = tid / 12, g = tid % 12;
        float m = 0.0f;
        for (int h = 0; h < 12; h++) m += reattn[p*144 + h*12 + g];
        smix[tid] = m;
    }
    __syncthreads();
    if (tid < 24) {
        int p = tid / 12;
        float mean = 0.0f, var = 0.0f;
        for (int g = 0; g < 12; g++) mean += smix[p*12+g];
        mean *= (1.0f/12.0f);
        for (int g = 0; g < 12; g++) { float d = smix[p*12+g]-mean; var += d*d; }
        var *= (1.0f/12.0f);
        float rs = rsqrtf(var + 1e-5f);
        g_w[tid] = (smix[tid]-mean)*rs*rng[tid] + rnb[tid];
    }
}

// ---------------- LN of x -> xa (f32) and xm (bf16 hi/lo) ----------------
__global__ void ln_x_kernel(const float* __restrict__ x,
                            const float* __restrict__ g1, const float* __restrict__ b1,
                            const float* __restrict__ g2, const float* __restrict__ b2) {
    __shared__ float sh1[33], sh2[33];
    int row = blockIdx.x, tid = threadIdx.x;
    const float* xr = x + (size_t)row * DD;
    float s = 0.0f, s2 = 0.0f;
    #pragma unroll
    for (int c = tid; c < DD; c += 256) { float v = xr[c]; s += v; s2 += v*v; }
    int lane = tid & 31, warp = tid >> 5;
    #pragma unroll
    for (int o = 16; o; o >>= 1) { s += __shfl_down_sync(~0u, s, o); s2 += __shfl_down_sync(~0u, s2, o); }
    if (lane == 0) { sh1[warp] = s; sh2[warp] = s2; }
    __syncthreads();
    if (warp == 0) {
        s  = (lane < 8) ? sh1[lane] : 0.0f;
        s2 = (lane < 8) ? sh2[lane] : 0.0f;
        #pragma unroll
        for (int o = 4; o; o >>= 1) { s += __shfl_down_sync(~0u, s, o); s2 += __shfl_down_sync(~0u, s2, o); }
        if (lane == 0) { sh1[32] = s; sh2[32] = s2; }
    }
    __syncthreads();
    float mean = sh1[32] * (1.0f/DD);
    float var  = sh2[32] * (1.0f/DD) - mean*mean;
    float rs = rsqrtf(var + 1e-5f);
    #pragma unroll
    for (int c = tid; c < DD; c += 256) {
        float v = (xr[c] - mean) * rs;
        g_xa[(size_t)row*DD + c] = v * g1[c] + b1[c];
        float m = v * g2[c] + b2[c];
        __nv_bfloat16 h, l; split_bf16(m, h, l);
        g_xmh[(size_t)row*DD + c] = h;
        g_xml[(size_t)row*DD + c] = l;
    }
}

// ---------------- split of x -> cols 768..1535 of wide A ----------------
__global__ void xsplit_kernel(const float* __restrict__ x) {
    int c = blockIdx.x * 256 + threadIdx.x;
    int row = blockIdx.y;
    float v = x[(size_t)row*DD + c];
    __nv_bfloat16 h, l; split_bf16(v, h, l);
    g_axh[(size_t)row*C2 + DD + c] = h;
    g_axl[(size_t)row*C2 + DD + c] = l;
}

// ---------------- LN of gate half of h ----------------
__global__ void ln_g_kernel(const float* __restrict__ gg, const float* __restrict__ gb) {
    __shared__ float sh1[33], sh2[33];
    int row = blockIdx.x, tid = threadIdx.x;
    const float* xr = g_h + (size_t)row * CC + C2;
    float s = 0.0f, s2 = 0.0f;
    #pragma unroll
    for (int c = tid; c < C2; c += 256) { float v = xr[c]; s += v; s2 += v*v; }
    int lane = tid & 31, warp = tid >> 5;
    #pragma unroll
    for (int o = 16; o; o >>= 1) { s += __shfl_down_sync(~0u, s, o); s2 += __shfl_down_sync(~0u, s2, o); }
    if (lane == 0) { sh1[warp] = s; sh2[warp] = s2; }
    __syncthreads();
    if (warp == 0) {
        s  = (lane < 8) ? sh1[lane] : 0.0f;
        s2 = (lane < 8) ? sh2[lane] : 0.0f;
        #pragma unroll
        for (int o = 4; o; o >>= 1) { s += __shfl_down_sync(~0u, s, o); s2 += __shfl_down_sync(~0u, s2, o); }
        if (lane == 0) { sh1[32] = s; sh2[32] = s2; }
    }
    __syncthreads();
    float mean = sh1[32] * (1.0f/C2);
    float var  = sh2[32] * (1.0f/C2) - mean*mean;
    float rs = rsqrtf(var + 1e-5f);
    #pragma unroll
    for (int c = tid; c < C2; c += 256) {
        float v = (xr[c] - mean) * rs;
        g_xgln[(size_t)row*C2 + c] = v * gg[c] + gb[c];
    }
}

// ---------------- fp32 SGEMM, K-split into 8 segments (R65 reduction) ----------------
__global__ __launch_bounds__(256) void sgemm_part(
    const float* __restrict__ A, const float* __restrict__ B, float* __restrict__ Cp,
    int K, int ldb, int ldc, size_t bStride)
{
    __shared__ float As[8][128];
    __shared__ float Bs[8][128];
    int seg = blockIdx.y, bz = blockIdx.z;
    B += (size_t)bz * bStride;
    float* C = Cp + (size_t)seg * (BB*128*DD) + (size_t)bz * (128*DD);
    int kbase = seg * (K / KSEG);
    int tid = threadIdx.x;
    int n0 = blockIdx.x * 128;
    int aRow = tid >> 1, aCol = (tid & 1) * 4;
    int bRow = tid >> 5, bCol = (tid & 31) * 4;
    const float* Ag = A + (size_t)aRow * K + kbase + aCol;
    const float* Bg = B + (size_t)(kbase + bRow) * ldb + n0 + bCol;
    float acc[8][8];
    #pragma unroll
    for (int i = 0; i < 8; i++)
        #pragma unroll
        for (int j = 0; j < 8; j++) acc[i][j] = 0.0f;
    int ty = tid >> 4, tx = tid & 15;
    for (int k0 = 0; k0 < K / KSEG; k0 += 8) {
        float4 av = *(const float4*)(Ag + k0);
        As[aCol+0][aRow] = av.x; As[aCol+1][aRow] = av.y;
        As[aCol+2][aRow] = av.z; As[aCol+3][aRow] = av.w;
        float4 bv = *(const float4*)(Bg + (size_t)k0 * ldb);
        *(float4*)&Bs[bRow][bCol] = bv;
        __syncthreads();
        #pragma unroll
        for (int kk = 0; kk < 8; kk++) {
            float a[8], b[8];
            *(float4*)(a)   = *(const float4*)&As[kk][ty*8];
            *(float4*)(a+4) = *(const float4*)&As[kk][ty*8+4];
            *(float4*)(b)   = *(const float4*)&Bs[kk][tx*8];
            *(float4*)(b+4) = *(const float4*)&Bs[kk][tx*8+4];
            #pragma unroll
            for (int i = 0; i < 8; i++)
                #pragma unroll
                for (int j = 0; j < 8; j++)
                    acc[i][j] += a[i] * b[j];
        }
        __syncthreads();
    }
    #pragma unroll
    for (int i = 0; i < 8; i++) {
        int r = ty*8 + i;
        #pragma unroll
        for (int j = 0; j < 8; j++)
            C[(size_t)r*ldc + n0 + tx*8 + j] = acc[i][j];
    }
}

__global__ void r65red_kernel() {
    int idx = blockIdx.x * 256 + threadIdx.x;   // BB*128*DD total
    float s = 0.0f;
    #pragma unroll
    for (int seg = 0; seg < KSEG; seg++)
        s += g_R65p[(size_t)seg * (BB*128*DD) + idx];
    g_R65[idx] = s;
}

// ---------------- vsum: warp-per-output using transposed Wv ----------------
__global__ void vsum2_kernel(const float* __restrict__ bqkv) {
    int gw = (blockIdx.x * blockDim.x + threadIdx.x) >> 5;
    int lane = threadIdx.x & 31;
    int j = gw % DD;
    int b = (gw / DD) & 3;
    int p = gw / (4 * DD);
    const float* bv = bqkv + p * (3*DD) + 2*DD;
    const float* R  = g_R65 + (size_t)b * 128 * DD;
    const float* Wt = g_wvt + (size_t)p * DD * DD;
    int c = j & 63;
    float acc = 0.0f;
    if (c < 32) {
        int t = c >> 1;
        int r1, r2, j2; float sgn;
        if (!(c & 1)) { r1 = 4*t;   r2 = 4*t+1; j2 = j+1; sgn = -1.0f; }
        else          { r1 = 4*t+2; r2 = 4*t+3; j2 = j-1; sgn =  1.0f; }
        const float* R1 = R + (size_t)r1 * DD;
        const float* R2 = R + (size_t)r2 * DD;
        const float* Wa = Wt + (size_t)j  * DD;
        const float* Wb = Wt + (size_t)j2 * DD;
        float a1 = 0.0f, a2 = 0.0f;
        for (int k = lane; k < DD; k += 32) { a1 += Wa[k]*R1[k]; a2 += Wb[k]*R2[k]; }
        acc = a1 + sgn * a2;
        #pragma unroll
        for (int o = 16; o; o >>= 1) acc += __shfl_down_sync(~0u, acc, o);
        if (lane == 0) acc += bv[j]*g_csum[r1] + sgn*bv[j2]*g_csum[r2];
    } else {
        const float* Rr = R + (size_t)64 * DD;
        const float* Wa = Wt + (size_t)j * DD;
        float a = 0.0f;
        for (int k = lane; k < DD; k += 32) a += Wa[k]*Rr[k];
        #pragma unroll
        for (int o = 16; o; o >>= 1) a += __shfl_down_sync(~0u, a, o);
        if (lane == 0) acc = a + bv[j]*g_csum[64];
    }
    if (lane == 0) g_vsum[((size_t)p*BB + b)*DD + j] = acc;
}

// ---------------- attn vector (constant over sequence) ----------------
__global__ void attnvec_kernel(const float* __restrict__ Wproj, const float* __restrict__ bproj) {
    __shared__ float yv[2*DD];
    int b = blockIdx.x, tid = threadIdx.x;
    #pragma unroll
    for (int p = 0; p < 2; p++)
        yv[p*DD + tid] = g_w[p*HH + (tid >> 6)] * g_vsum[((size_t)p*BB + b)*DD + tid];
    __syncthreads();
    float acc = 0.0f;
    #pragma unroll
    for (int p = 0; p < 2; p++) {
        acc += bproj[p*DD + tid];
        const float* Wp = Wproj + (size_t)p * DD * DD;
        const float* y = yv + p*DD;
        for (int jj = 0; jj < DD; jj++)
            acc += y[jj] * Wp[(size_t)jj*DD + tid];
    }
    g_attn[(size_t)b*DD + tid] = acc;
}

// ---------------- bb[b][c] = bout[c] + sum_k ls1[k]*attn[b][k]*Wout[k][c] ----------------
__global__ void bb_kernel(const float* __restrict__ Wout, const float* __restrict__ bout,
                          const float* __restrict__ ls1) {
    __shared__ float cv[DD];
    int b = blockIdx.x, c = threadIdx.x;
    cv[c] = ls1[c] * g_attn[(size_t)b*DD + c];
    __syncthreads();
    float acc = bout[c];
    for (int k = 0; k < DD; k++)
        acc += cv[k] * Wout[(size_t)k*DD + c];
    g_bb[(size_t)b*DD + c] = acc;
}

// ---------------- tiled depthwise conv (K=21) + gate -> u bf16 hi/lo ----------------
__global__ __launch_bounds__(256) void conv_kernel(const float* __restrict__ cw,
                                                   const float* __restrict__ cb) {
    __shared__ float sx[84*64];
    __shared__ float scw[64*21];
    int ch0 = blockIdx.x * 64;
    int r0  = blockIdx.y * 64;
    int tid = threadIdx.x;
    for (int q = tid; q < 64*21; q += 256) {
        int ch = q / 21, k = q % 21;
        scw[ch*21 + k] = cw[(size_t)(ch0 + ch)*21 + k];
    }
    int b = r0 >> 10, i0 = r0 & 1023;
    for (int q = tid; q < 84*64; q += 256) {
        int rr = q >> 6, ch = q & 63;
        int ii = i0 - 10 + rr;
        sx[rr*64 + ch] = (ii >= 0 && ii < NN)
            ? g_xgln[((size_t)((b << 10) + ii))*C2 + ch0 + ch] : 0.0f;
    }
    __syncthreads();
    int ch = tid & 63, ty = tid >> 6;
    float cbv = cb[ch0 + ch];
    float w[21];
    #pragma unroll
    for (int k = 0; k < 21; k++) w[k] = scw[ch*21 + k];
    for (int rg = 0; rg < 16; rg++) {
        int r = ty*16 + rg;
        float acc = cbv;
        #pragma unroll
        for (int k = 0; k < 21; k++)
            acc += w[k] * sx[(r + k)*64 + ch];
        int row = r0 + r;
        float v = g_h[(size_t)row*CC + ch0 + ch] * acc;
        __nv_bfloat16 h, l; split_bf16(v, h, l);
        g_uh[(size_t)row*C2 + ch0 + ch] = h;
        g_ul[(size_t)row*C2 + ch0 + ch] = l;
    }
}

// ---------------- launch ----------------
extern "C" void kernel_launch(void* const* d_in, const int* in_sizes, int n_in,
                              void* d_out, int out_size) {
    const float* x      = (const float*)d_in[0];
    const float* Wqkv   = (const float*)d_in[1];
    const float* bqkv   = (const float*)d_in[2];
    const float* Wproj  = (const float*)d_in[3];
    const float* bproj  = (const float*)d_in[4];
    const float* reattn = (const float*)d_in[9];
    const float* rn_g   = (const float*)d_in[10];
    const float* rn_b   = (const float*)d_in[11];
    const float* ln1_g  = (const float*)d_in[12];
    const float* ln1_b  = (const float*)d_in[13];
    const float* ln2_g  = (const float*)d_in[14];
    const float* ln2_b  = (const float*)d_in[15];
    const float* ls1    = (const float*)d_in[16];
    const float* ls2    = (const float*)d_in[17];
    const float* W1     = (const float*)d_in[18];
    const float* b1     = (const float*)d_in[19];
    const float* gn_g   = (const float*)d_in[20];
    const float* gn_b   = (const float*)d_in[21];
    const float* conv_w = (const float*)d_in[22];
    const float* conv_b = (const float*)d_in[23];
    const float* W2     = (const float*)d_in[24];
    const float* b2     = (const float*)d_in[25];
    const float* Wout   = (const float*)d_in[26];
    const float* bout   = (const float*)d_in[27];
    float* out = (float*)d_out;

    float *xa, *CT, *R65p, *hbuf, *bb;
    __nv_bfloat16 *xmh, *xml, *w1h, *w1l, *w2h, *w2l, *wch, *wcl;
    __nv_bfloat16 *uh, *ul, *axh, *axl;
    cudaGetSymbolAddress((void**)&xa,    g_xa);
    cudaGetSymbolAddress((void**)&CT,    g_CT);
    cudaGetSymbolAddress((void**)&R65p,  g_R65p);
    cudaGetSymbolAddress((void**)&hbuf,  g_h);
    cudaGetSymbolAddress((void**)&bb,    g_bb);
    cudaGetSymbolAddress((void**)&xmh,   g_xmh);  cudaGetSymbolAddress((void**)&xml, g_xml);
    cudaGetSymbolAddress((void**)&w1h,   g_w1h);  cudaGetSymbolAddress((void**)&w1l, g_w1l);
    cudaGetSymbolAddress((void**)&w2h,   g_w2h);  cudaGetSymbolAddress((void**)&w2l, g_w2l);
    cudaGetSymbolAddress((void**)&wch,   g_wch);  cudaGetSymbolAddress((void**)&wcl, g_wcl);
    cudaGetSymbolAddress((void**)&uh,    g_uh);   cudaGetSymbolAddress((void**)&ul,  g_ul);
    cudaGetSymbolAddress((void**)&axh,   g_axh);  cudaGetSymbolAddress((void**)&axl, g_axl);

    dim3 t32x8(32, 8);
    // weight prep
    prep_kernel<<<1, 1024>>>(reattn, rn_g, rn_b);
    wsplit_kernel<<<dim3(CC/32, DD/32), t32x8>>>(W1, w1h, w1l, DD, CC);
    wsplit_kernel<<<dim3(DD/32, C2/32), t32x8>>>(W2, w2h, w2l, C2, DD);
    wsum_kernel<<<dim3(DD/32, DD/32), t32x8>>>(Wout);
    wscale_kernel<<<dim3(DD/32, DD/32), t32x8>>>(Wout, ls2);
    wvt_kernel<<<dim3(DD/32, DD/32, 2), t32x8>>>(Wqkv);

    // LN + split of x into wide A cols 768..1535
    ln_x_kernel<<<ROWS, 256>>>(x, ln1_g, ln1_b, ln2_g, ln2_b);
    xsplit_kernel<<<dim3(3, ROWS), 256>>>(x);

    // attention path (exact fp32, constant over sequence)
    sgemm_part<<<dim3(6, KSEG, 4), 256>>>(CT, xa, R65p, NN, DD, DD, (size_t)NN*DD);
    r65red_kernel<<<(BB*128*DD)/256, 256>>>();
    vsum2_kernel<<<768, 256>>>(bqkv);
    attnvec_kernel<<<4, 768>>>(Wproj, bproj);
    bb_kernel<<<4, 768>>>(Wout, bout, ls1);

    // h = gelu(xm @ W1 + b1)
    mma_gemm<<<dim3(CC/128, ROWS/128), 256>>>(
        xmh, xml, w1h, w1l, DD, hbuf, CC,
        nullptr, nullptr, 0, b1, nullptr, nullptr, 0, 1);
    ln_g_kernel<<<ROWS, 256>>>(gn_g, gn_b);
    conv_kernel<<<dim3(C2/64, ROWS/64), 256>>>(conv_w, conv_b);
    // m = u @ W2 + b2 -> bf16 split into wide A cols 0..767
    mma_gemm<<<dim3(DD/128, ROWS/128), 256>>>(
        uh, ul, w2h, w2l, C2, nullptr, 0,
        axh, axl, C2, b2, nullptr, nullptr, 0, 2);
    // out = [m|x] @ [Wb'|Ws]^T + x + bb[batch]
    mma_gemm<<<dim3(DD/128, ROWS/128), 256>>>(
        axh, axl, wch, wcl, C2, out, DD,
        nullptr, nullptr, 0, nullptr, bb, x, DD, 4);
}

// round 15
// speedup vs baseline: 1.4602x; 1.3560x over previous
#include <cuda_runtime.h>
#include <cuda_bf16.h>
#include <math.h>
#include <stdint.h>

#define BB 4
#define NN 1024
#define DD 768
#define HH 12
#define CC 3072
#define C2 1536
#define ROWS (BB*NN)
#define KSEG 8

// ---------------- fp32 scratch ----------------
__device__ float g_xa[ROWS*DD];
__device__ float g_CT[128*NN];
__device__ float g_csum[65];
__device__ float g_R65p[KSEG*BB*128*DD];
__device__ float g_R65[BB*128*DD];
__device__ float g_wvt[2*DD*DD];
__device__ float g_vsum[2*BB*DD];
__device__ float g_w[2*HH];
__device__ float g_attn[BB*DD];
__device__ float g_bb[BB*DD];
__device__ float g_h[ROWS*CC];
__device__ float g_xgln[ROWS*C2];

// ---------------- bf16 buffers (hi-only where MLP damping allows) ----------------
__device__ __align__(16) __nv_bfloat16 g_xmh[ROWS*DD];
__device__ __align__(16) __nv_bfloat16 g_w1h[CC*DD];
__device__ __align__(16) __nv_bfloat16 g_w2h[DD*C2];
__device__ __align__(16) __nv_bfloat16 g_wch[DD*C2],   g_wcl[DD*C2];   // [N=768, K=1536] = [Wb' | Ws]
__device__ __align__(16) __nv_bfloat16 g_uh[ROWS*C2];
__device__ __align__(16) __nv_bfloat16 g_axh[ROWS*C2], g_axl[ROWS*C2]; // [m | x] wide A buffer

__device__ __forceinline__ float geluf(float v) {
    return 0.5f * v * (1.0f + erff(v * 0.7071067811865476f));
}
__device__ __forceinline__ void split_bf16(float v, __nv_bfloat16& h, __nv_bfloat16& l) {
    h = __float2bfloat16(v);
    l = __float2bfloat16(v - __bfloat162float(h));
}

// ================= mma.sync helpers ====
__device__ __forceinline__ void ldsm_x4(uint32_t& r0, uint32_t& r1, uint32_t& r2, uint32_t& r3, uint32_t a) {
    asm volatile("ldmatrix.sync.aligned.m8n8.x4.shared.b16 {%0,%1,%2,%3}, [%4];"
        : "=r"(r0), "=r"(r1), "=r"(r2), "=r"(r3) : "r"(a));
}
__device__ __forceinline__ void mma_bf16(float* d, const uint32_t* a, const uint32_t* b) {
    asm volatile("mma.sync.aligned.m16n8k16.row.col.f32.bf16.bf16.f32 "
        "{%0,%1,%2,%3}, {%4,%5,%6,%7}, {%8,%9}, {%0,%1,%2,%3};"
        : "+f"(d[0]), "+f"(d[1]), "+f"(d[2]), "+f"(d[3])
        : "r"(a[0]), "r"(a[1]), "r"(a[2]), "r"(a[3]), "r"(b[0]), "r"(b[1]));
}
__device__ __forceinline__ void cp16(uint32_t s, const void* g) {
    asm volatile("cp.async.cg.shared.global [%0], [%1], 16;" :: "r"(s), "l"(g));
}
#define CP_COMMIT() asm volatile("cp.async.commit_group;" ::: "memory")
#define CP_WAIT1()  asm volatile("cp.async.wait_group 1;" ::: "memory")

// ================= split-bf16 GEMM: D = A @ B^T =============
// A: [M,K] K-major bf16 hi/lo.  B: [N,K] K-major bf16 hi/lo.
// Tile 128x128, K chunk 32, 256 thr, static double-buffered cp.async.
// nPhase=3: Ah.Bh + Ah.Bl + Al.Bh (split-fp32 accuracy).
// nPhase=1: Ah.Bh only (pure bf16 — for the ls2-damped MLP path).
// modes: 1: C = gelu(v+bias)              (f32)
//        2: split(v+bias) -> Cbh/Cbl      (bf16 pair)
//        4: C = v + resid + bias2[(row>>10)*768 + col]
#define SROW 40   // padded row stride in bf16 elems (80B: conflict-free ldmatrix)
__global__ __launch_bounds__(256) void mma_gemm(
    const __nv_bfloat16* __restrict__ Ah, const __nv_bfloat16* __restrict__ Al,
    const __nv_bfloat16* __restrict__ Bh, const __nv_bfloat16* __restrict__ Bl,
    int K, int nPhase,
    float* __restrict__ C, int ldc,
    __nv_bfloat16* __restrict__ Cbh, __nv_bfloat16* __restrict__ Cbl, int ldcb,
    const float* __restrict__ bias, const float* __restrict__ bias2,
    const float* __restrict__ resid, int ldr, int mode)
{
    __shared__ __align__(16) __nv_bfloat16 sA[2][128*SROW];
    __shared__ __align__(16) __nv_bfloat16 sB[2][128*SROW];
    const int tid = threadIdx.x, lane = tid & 31, wid = tid >> 5;
    const int m0 = blockIdx.y * 128, n0 = blockIdx.x * 128;
    const int wm = wid >> 1, wn = wid & 1;            // 4x2 warp grid
    const int mb = wm * 32, nb = wn * 64;

    float acc[2][8][4];
    #pragma unroll
    for (int i = 0; i < 2; i++)
        #pragma unroll
        for (int j = 0; j < 8; j++)
            #pragma unroll
            for (int q = 0; q < 4; q++) acc[i][j][q] = 0.0f;

    const int kSteps = K >> 5, nIter = nPhase * kSteps;
    const int lr = tid >> 2, lc = (tid & 3) * 8;      // cp.async mapping

    auto loadStage = [&](int iter, int st) {
        int ph = iter / kSteps, kc = iter % kSteps;
        const __nv_bfloat16* A = (ph < 2) ? Ah : Al;
        const __nv_bfloat16* B = (ph == 1) ? Bl : Bh;
        int k0 = kc << 5;
        uint32_t sa = (uint32_t)__cvta_generic_to_shared(&sA[st][0]);
        uint32_t sb = (uint32_t)__cvta_generic_to_shared(&sB[st][0]);
        cp16(sa + (lr*SROW + lc)*2,        A + (size_t)(m0 + lr)      * K + k0 + lc);
        cp16(sa + ((lr+64)*SROW + lc)*2,   A + (size_t)(m0 + lr + 64) * K + k0 + lc);
        cp16(sb + (lr*SROW + lc)*2,        B + (size_t)(n0 + lr)      * K + k0 + lc);
        cp16(sb + ((lr+64)*SROW + lc)*2,   B + (size_t)(n0 + lr + 64) * K + k0 + lc);
    };

    loadStage(0, 0);
    CP_COMMIT();
    for (int i = 0; i < nIter; i++) {
        if (i + 1 < nIter) loadStage(i + 1, (i + 1) & 1);
        CP_COMMIT();
        CP_WAIT1();
        __syncthreads();
        int st = i & 1;
        uint32_t sa = (uint32_t)__cvta_generic_to_shared(&sA[st][0]);
        uint32_t sb = (uint32_t)__cvta_generic_to_shared(&sB[st][0]);
        #pragma unroll
        for (int ks = 0; ks < 2; ks++) {
            int kl = ks * 16;
            uint32_t af[2][4];
            #pragma unroll
            for (int mt = 0; mt < 2; mt++) {
                int row = mb + mt*16 + (lane & 15);
                int ko  = kl + ((lane >> 4) << 3);
                ldsm_x4(af[mt][0], af[mt][1], af[mt][2], af[mt][3],
                        sa + (uint32_t)(row*SROW + ko)*2);
            }
            uint32_t bf[8][2];
            #pragma unroll
            for (int nt4 = 0; nt4 < 4; nt4++) {
                int nrow = nb + nt4*16 + (lane & 7) + ((lane >> 4) << 3);
                int ko   = kl + (((lane >> 3) & 1) << 3);
                uint32_t r0, r1, r2, r3;
                ldsm_x4(r0, r1, r2, r3, sb + (uint32_t)(nrow*SROW + ko)*2);
                bf[nt4*2][0] = r0; bf[nt4*2][1] = r1;
                bf[nt4*2+1][0] = r2; bf[nt4*2+1][1] = r3;
            }
            #pragma unroll
            for (int mt = 0; mt < 2; mt++)
                #pragma unroll
                for (int nt = 0; nt < 8; nt++)
                    mma_bf16(acc[mt][nt], af[mt], bf[nt]);
        }
        __syncthreads();
    }

    // epilogue
    #pragma unroll
    for (int mt = 0; mt < 2; mt++) {
        #pragma unroll
        for (int nt = 0; nt < 8; nt++) {
            int row = m0 + mb + mt*16 + (lane >> 2);
            int col = n0 + nb + nt*8 + (lane & 3)*2;
            #pragma unroll
            for (int h = 0; h < 2; h++) {
                int rr = row + h*8;
                #pragma unroll
                for (int q = 0; q < 2; q++) {
                    int cc = col + q;
                    float v = acc[mt][nt][h*2 + q];
                    if (mode == 1) {
                        C[(size_t)rr*ldc + cc] = geluf(v + bias[cc]);
                    } else if (mode == 2) {
                        float o = v + bias[cc];
                        __nv_bfloat16 hh, ll; split_bf16(o, hh, ll);
                        Cbh[(size_t)rr*ldcb + cc] = hh;
                        Cbl[(size_t)rr*ldcb + cc] = ll;
                    } else {
                        C[(size_t)rr*ldc + cc] = v + resid[(size_t)rr*ldr + cc]
                                               + bias2[(size_t)(rr >> 10)*DD + cc];
                    }
                }
            }
        }
    }
}

// ================= weight prep =================
// hi-only transpose split: W[K,N] f32 -> Wh[N,K] bf16
__global__ void wsplit_h_kernel(const float* __restrict__ W,
                                __nv_bfloat16* __restrict__ Wh, int K, int N) {
    __shared__ float t[32][33];
    int n0 = blockIdx.x * 32, k0 = blockIdx.y * 32;
    int tx = threadIdx.x, ty = threadIdx.y;
    for (int i = ty; i < 32; i += 8) t[i][tx] = W[(size_t)(k0 + i) * N + n0 + tx];
    __syncthreads();
    for (int i = ty; i < 32; i += 8)
        Wh[(size_t)(n0 + i) * K + k0 + tx] = __float2bfloat16(t[tx][i]);
}

// Ws = Wout[0:768]+Wout[768:1536] -> cols 768..1535 of concat B [768,1536]
__global__ void wsum_kernel(const float* __restrict__ Wout) {
    __shared__ float t[32][33];
    int n0 = blockIdx.x * 32, k0 = blockIdx.y * 32;
    int tx = threadIdx.x, ty = threadIdx.y;
    for (int i = ty; i < 32; i += 8)
        t[i][tx] = Wout[(size_t)(k0 + i) * DD + n0 + tx]
                 + Wout[(size_t)(DD + k0 + i) * DD + n0 + tx];
    __syncthreads();
    for (int i = ty; i < 32; i += 8) {
        float v = t[tx][i];
        __nv_bfloat16 h, l; split_bf16(v, h, l);
        g_wch[(size_t)(n0 + i) * C2 + DD + k0 + tx] = h;
        g_wcl[(size_t)(n0 + i) * C2 + DD + k0 + tx] = l;
    }
}

// Wb' = diag(ls2)*Wout[768:1536] -> cols 0..767 of concat B
__global__ void wscale_kernel(const float* __restrict__ Wout, const float* __restrict__ ls2) {
    __shared__ float t[32][33];
    int n0 = blockIdx.x * 32, k0 = blockIdx.y * 32;
    int tx = threadIdx.x, ty = threadIdx.y;
    for (int i = ty; i < 32; i += 8)
        t[i][tx] = ls2[k0 + i] * Wout[(size_t)(DD + k0 + i) * DD + n0 + tx];
    __syncthreads();
    for (int i = ty; i < 32; i += 8) {
        float v = t[tx][i];
        __nv_bfloat16 h, l; split_bf16(v, h, l);
        g_wch[(size_t)(n0 + i) * C2 + k0 + tx] = h;
        g_wcl[(size_t)(n0 + i) * C2 + k0 + tx] = l;
    }
}

__global__ void wvt_kernel(const float* __restrict__ Wqkv) {
    __shared__ float t[32][33];
    int p = blockIdx.z;
    const float* W = Wqkv + (size_t)p * DD * (3*DD) + 2*DD;
    int j0 = blockIdx.x * 32, k0 = blockIdx.y * 32;
    int tx = threadIdx.x, ty = threadIdx.y;
    for (int i = ty; i < 32; i += 8) t[i][tx] = W[(size_t)(k0 + i) * (3*DD) + j0 + tx];
    __syncthreads();
    for (int i = ty; i < 32; i += 8)
        g_wvt[(size_t)p * DD * DD + (size_t)(j0 + i) * DD + k0 + tx] = t[tx][i];
}

// ---------------- prep: rope coef table + reattn weights ----------------
__global__ void prep_kernel(const float* __restrict__ reattn,
                            const float* __restrict__ rng,
                            const float* __restrict__ rnb) {
    __shared__ float smix[24];
    int tid = threadIdx.x;
    float fi = (float)tid;
    float power = (fi - 512.0f) / 512.0f;
    #pragma unroll
    for (int t = 0; t < 16; t++) {
        float inv = powf(10000.0f, -(float)t / 16.0f);
        float fr = fi * inv;
        float c = cosf(fr), s = sinf(fr);
        int u1 = (2*t) & 15, u2 = (2*t+1) & 15;
        float sA = powf((2.0f*u1 + 12.8f) / 44.8f, -power);
        float sB = powf((2.0f*u2 + 12.8f) / 44.8f, -power);
        g_CT[(4*t+0)*NN + tid] = sA * c;
        g_CT[(4*t+1)*NN + tid] = sA * s;
        g_CT[(4*t+2)*NN + tid] = sB * c;
        g_CT[(4*t+3)*NN + tid] = sB * s;
    }
    g_CT[64*NN + tid] = 1.0f;
    __syncthreads();
    int warp = tid >> 5, lane = tid & 31;
    for (int c = warp; c < 65; c += 32) {
        float s = 0.0f;
        for (int q = lane; q < NN; q += 32) s += g_CT[c*NN + q];
        #pragma unroll
        for (int o = 16; o; o >>= 1) s += __shfl_down_sync(0xffffffffu, s, o);
        if (lane == 0) g_csum[c] = s;
    }
    if (tid < 24) {
        int p = tid / 12, g = tid % 12;
        float m = 0.0f;
        for (int h = 0; h < 12; h++) m += reattn[p*144 + h*12 + g];
        smix[tid] = m;
    }
    __syncthreads();
    if (tid < 24) {
        int p = tid / 12;
        float mean = 0.0f, var = 0.0f;
        for (int g = 0; g < 12; g++) mean += smix[p*12+g];
        mean *= (1.0f/12.0f);
        for (int g = 0; g < 12; g++) { float d = smix[p*12+g]-mean; var += d*d; }
        var *= (1.0f/12.0f);
        float rs = rsqrtf(var + 1e-5f);
        g_w[tid] = (smix[tid]-mean)*rs*rng[tid] + rnb[tid];
    }
}

// ---------------- LN of x -> xa (f32) and xm (bf16 hi) ----------------
__global__ void ln_x_kernel(const float* __restrict__ x,
                            const float* __restrict__ g1, const float* __restrict__ b1,
                            const float* __restrict__ g2, const float* __restrict__ b2) {
    __shared__ float sh1[33], sh2[33];
    int row = blockIdx.x, tid = threadIdx.x;
    const float* xr = x + (size_t)row * DD;
    float s = 0.0f, s2 = 0.0f;
    #pragma unroll
    for (int c = tid; c < DD; c += 256) { float v = xr[c]; s += v; s2 += v*v; }
    int lane = tid & 31, warp = tid >> 5;
    #pragma unroll
    for (int o = 16; o; o >>= 1) { s += __shfl_down_sync(~0u, s, o); s2 += __shfl_down_sync(~0u, s2, o); }
    if (lane == 0) { sh1[warp] = s; sh2[warp] = s2; }
    __syncthreads();
    if (warp == 0) {
        s  = (lane < 8) ? sh1[lane] : 0.0f;
        s2 = (lane < 8) ? sh2[lane] : 0.0f;
        #pragma unroll
        for (int o = 4; o; o >>= 1) { s += __shfl_down_sync(~0u, s, o); s2 += __shfl_down_sync(~0u, s2, o); }
        if (lane == 0) { sh1[32] = s; sh2[32] = s2; }
    }
    __syncthreads();
    float mean = sh1[32] * (1.0f/DD);
    float var  = sh2[32] * (1.0f/DD) - mean*mean;
    float rs = rsqrtf(var + 1e-5f);
    #pragma unroll
    for (int c = tid; c < DD; c += 256) {
        float v = (xr[c] - mean) * rs;
        g_xa[(size_t)row*DD + c] = v * g1[c] + b1[c];
        g_xmh[(size_t)row*DD + c] = __float2bfloat16(v * g2[c] + b2[c]);
    }
}

// ---------------- split of x -> cols 768..1535 of wide A ----------------
__global__ void xsplit_kernel(const float* __restrict__ x) {
    int c = blockIdx.x * 256 + threadIdx.x;
    int row = blockIdx.y;
    float v = x[(size_t)row*DD + c];
    __nv_bfloat16 h, l; split_bf16(v, h, l);
    g_axh[(size_t)row*C2 + DD + c] = h;
    g_axl[(size_t)row*C2 + DD + c] = l;
}

// ---------------- LN of gate half of h ----------------
__global__ void ln_g_kernel(const float* __restrict__ gg, const float* __restrict__ gb) {
    __shared__ float sh1[33], sh2[33];
    int row = blockIdx.x, tid = threadIdx.x;
    const float* xr = g_h + (size_t)row * CC + C2;
    float s = 0.0f, s2 = 0.0f;
    #pragma unroll
    for (int c = tid; c < C2; c += 256) { float v = xr[c]; s += v; s2 += v*v; }
    int lane = tid & 31, warp = tid >> 5;
    #pragma unroll
    for (int o = 16; o; o >>= 1) { s += __shfl_down_sync(~0u, s, o); s2 += __shfl_down_sync(~0u, s2, o); }
    if (lane == 0) { sh1[warp] = s; sh2[warp] = s2; }
    __syncthreads();
    if (warp == 0) {
        s  = (lane < 8) ? sh1[lane] : 0.0f;
        s2 = (lane < 8) ? sh2[lane] : 0.0f;
        #pragma unroll
        for (int o = 4; o; o >>= 1) { s += __shfl_down_sync(~0u, s, o); s2 += __shfl_down_sync(~0u, s2, o); }
        if (lane == 0) { sh1[32] = s; sh2[32] = s2; }
    }
    __syncthreads();
    float mean = sh1[32] * (1.0f/C2);
    float var  = sh2[32] * (1.0f/C2) - mean*mean;
    float rs = rsqrtf(var + 1e-5f);
    #pragma unroll
    for (int c = tid; c < C2; c += 256) {
        float v = (xr[c] - mean) * rs;
        g_xgln[(size_t)row*C2 + c] = v * gg[c] + gb[c];
    }
}

// ---------------- fp32 SGEMM, K-split into 8 segments (R65 reduction) ----------------
__global__ __launch_bounds__(256) void sgemm_part(
    const float* __restrict__ A, const float* __restrict__ B, float* __restrict__ Cp,
    int K, int ldb, int ldc, size_t bStride)
{
    __shared__ float As[8][128];
    __shared__ float Bs[8][128];
    int seg = blockIdx.y, bz = blockIdx.z;
    B += (size_t)bz * bStride;
    float* C = Cp + (size_t)seg * (BB*128*DD) + (size_t)bz * (128*DD);
    int kbase = seg * (K / KSEG);
    int tid = threadIdx.x;
    int n0 = blockIdx.x * 128;
    int aRow = tid >> 1, aCol = (tid & 1) * 4;
    int bRow = tid >> 5, bCol = (tid & 31) * 4;
    const float* Ag = A + (size_t)aRow * K + kbase + aCol;
    const float* Bg = B + (size_t)(kbase + bRow) * ldb + n0 + bCol;
    float acc[8][8];
    #pragma unroll
    for (int i = 0; i < 8; i++)
        #pragma unroll
        for (int j = 0; j < 8; j++) acc[i][j] = 0.0f;
    int ty = tid >> 4, tx = tid & 15;
    for (int k0 = 0; k0 < K / KSEG; k0 += 8) {
        float4 av = *(const float4*)(Ag + k0);
        As[aCol+0][aRow] = av.x; As[aCol+1][aRow] = av.y;
        As[aCol+2][aRow] = av.z; As[aCol+3][aRow] = av.w;
        float4 bv = *(const float4*)(Bg + (size_t)k0 * ldb);
        *(float4*)&Bs[bRow][bCol] = bv;
        __syncthreads();
        #pragma unroll
        for (int kk = 0; kk < 8; kk++) {
            float a[8], b[8];
            *(float4*)(a)   = *(const float4*)&As[kk][ty*8];
            *(float4*)(a+4) = *(const float4*)&As[kk][ty*8+4];
            *(float4*)(b)   = *(const float4*)&Bs[kk][tx*8];
            *(float4*)(b+4) = *(const float4*)&Bs[kk][tx*8+4];
            #pragma unroll
            for (int i = 0; i < 8; i++)
                #pragma unroll
                for (int j = 0; j < 8; j++)
                    acc[i][j] += a[i] * b[j];
        }
        __syncthreads();
    }
    #pragma unroll
    for (int i = 0; i < 8; i++) {
        int r = ty*8 + i;
        #pragma unroll
        for (int j = 0; j < 8; j++)
            C[(size_t)r*ldc + n0 + tx*8 + j] = acc[i][j];
    }
}

__global__ void r65red_kernel() {
    int idx = blockIdx.x * 256 + threadIdx.x;   // BB*128*DD total
    float s = 0.0f;
    #pragma unroll
    for (int seg = 0; seg < KSEG; seg++)
        s += g_R65p[(size_t)seg * (BB*128*DD) + idx];
    g_R65[idx] = s;
}

// ---------------- vsum: warp-per-output using transposed Wv ----------------
__global__ void vsum2_kernel(const float* __restrict__ bqkv) {
    int gw = (blockIdx.x * blockDim.x + threadIdx.x) >> 5;
    int lane = threadIdx.x & 31;
    int j = gw % DD;
    int b = (gw / DD) & 3;
    int p = gw / (4 * DD);
    const float* bv = bqkv + p * (3*DD) + 2*DD;
    const float* R  = g_R65 + (size_t)b * 128 * DD;
    const float* Wt = g_wvt + (size_t)p * DD * DD;
    int c = j & 63;
    float acc = 0.0f;
    if (c < 32) {
        int t = c >> 1;
        int r1, r2, j2; float sgn;
        if (!(c & 1)) { r1 = 4*t;   r2 = 4*t+1; j2 = j+1; sgn = -1.0f; }
        else          { r1 = 4*t+2; r2 = 4*t+3; j2 = j-1; sgn =  1.0f; }
        const float* R1 = R + (size_t)r1 * DD;
        const float* R2 = R + (size_t)r2 * DD;
        const float* Wa = Wt + (size_t)j  * DD;
        const float* Wb = Wt + (size_t)j2 * DD;
        float a1 = 0.0f, a2 = 0.0f;
        for (int k = lane; k < DD; k += 32) { a1 += Wa[k]*R1[k]; a2 += Wb[k]*R2[k]; }
        acc = a1 + sgn * a2;
        #pragma unroll
        for (int o = 16; o; o >>= 1) acc += __shfl_down_sync(~0u, acc, o);
        if (lane == 0) acc += bv[j]*g_csum[r1] + sgn*bv[j2]*g_csum[r2];
    } else {
        const float* Rr = R + (size_t)64 * DD;
        const float* Wa = Wt + (size_t)j * DD;
        float a = 0.0f;
        for (int k = lane; k < DD; k += 32) a += Wa[k]*Rr[k];
        #pragma unroll
        for (int o = 16; o; o >>= 1) a += __shfl_down_sync(~0u, a, o);
        if (lane == 0) acc = a + bv[j]*g_csum[64];
    }
    if (lane == 0) g_vsum[((size_t)p*BB + b)*DD + j] = acc;
}

// ---------------- attn vector (constant over sequence) ----------------
__global__ void attnvec_kernel(const float* __restrict__ Wproj, const float* __restrict__ bproj) {
    __shared__ float yv[2*DD];
    int b = blockIdx.x, tid = threadIdx.x;
    #pragma unroll
    for (int p = 0; p < 2; p++)
        yv[p*DD + tid] = g_w[p*HH + (tid >> 6)] * g_vsum[((size_t)p*BB + b)*DD + tid];
    __syncthreads();
    float acc = 0.0f;
    #pragma unroll
    for (int p = 0; p < 2; p++) {
        acc += bproj[p*DD + tid];
        const float* Wp = Wproj + (size_t)p * DD * DD;
        const float* y = yv + p*DD;
        for (int jj = 0; jj < DD; jj++)
            acc += y[jj] * Wp[(size_t)jj*DD + tid];
    }
    g_attn[(size_t)b*DD + tid] = acc;
}

// ---------------- bb[b][c] = bout[c] + sum_k ls1[k]*attn[b][k]*Wout[k][c] ----------------
__global__ void bb_kernel(const float* __restrict__ Wout, const float* __restrict__ bout,
                          const float* __restrict__ ls1) {
    __shared__ float cv[DD];
    int b = blockIdx.x, c = threadIdx.x;
    cv[c] = ls1[c] * g_attn[(size_t)b*DD + c];
    __syncthreads();
    float acc = bout[c];
    for (int k = 0; k < DD; k++)
        acc += cv[k] * Wout[(size_t)k*DD + c];
    g_bb[(size_t)b*DD + c] = acc;
}

// ---------------- tiled depthwise conv (K=21) + gate -> u bf16 hi ----------------
__global__ __launch_bounds__(256) void conv_kernel(const float* __restrict__ cw,
                                                   const float* __restrict__ cb) {
    __shared__ float sx[84*64];
    __shared__ float scw[64*21];
    int ch0 = blockIdx.x * 64;
    int r0  = blockIdx.y * 64;
    int tid = threadIdx.x;
    for (int q = tid; q < 64*21; q += 256) {
        int ch = q / 21, k = q % 21;
        scw[ch*21 + k] = cw[(size_t)(ch0 + ch)*21 + k];
    }
    int b = r0 >> 10, i0 = r0 & 1023;
    for (int q = tid; q < 84*64; q += 256) {
        int rr = q >> 6, ch = q & 63;
        int ii = i0 - 10 + rr;
        sx[rr*64 + ch] = (ii >= 0 && ii < NN)
            ? g_xgln[((size_t)((b << 10) + ii))*C2 + ch0 + ch] : 0.0f;
    }
    __syncthreads();
    int ch = tid & 63, ty = tid >> 6;
    float cbv = cb[ch0 + ch];
    float w[21];
    #pragma unroll
    for (int k = 0; k < 21; k++) w[k] = scw[ch*21 + k];
    for (int rg = 0; rg < 16; rg++) {
        int r = ty*16 + rg;
        float acc = cbv;
        #pragma unroll
        for (int k = 0; k < 21; k++)
            acc += w[k] * sx[(r + k)*64 + ch];
        int row = r0 + r;
        float v = g_h[(size_t)row*CC + ch0 + ch] * acc;
        g_uh[(size_t)row*C2 + ch0 + ch] = __float2bfloat16(v);
    }
}

// ---------------- launch ----------------
extern "C" void kernel_launch(void* const* d_in, const int* in_sizes, int n_in,
                              void* d_out, int out_size) {
    const float* x      = (const float*)d_in[0];
    const float* Wqkv   = (const float*)d_in[1];
    const float* bqkv   = (const float*)d_in[2];
    const float* Wproj  = (const float*)d_in[3];
    const float* bproj  = (const float*)d_in[4];
    const float* reattn = (const float*)d_in[9];
    const float* rn_g   = (const float*)d_in[10];
    const float* rn_b   = (const float*)d_in[11];
    const float* ln1_g  = (const float*)d_in[12];
    const float* ln1_b  = (const float*)d_in[13];
    const float* ln2_g  = (const float*)d_in[14];
    const float* ln2_b  = (const float*)d_in[15];
    const float* ls1    = (const float*)d_in[16];
    const float* ls2    = (const float*)d_in[17];
    const float* W1     = (const float*)d_in[18];
    const float* b1     = (const float*)d_in[19];
    const float* gn_g   = (const float*)d_in[20];
    const float* gn_b   = (const float*)d_in[21];
    const float* conv_w = (const float*)d_in[22];
    const float* conv_b = (const float*)d_in[23];
    const float* W2     = (const float*)d_in[24];
    const float* b2     = (const float*)d_in[25];
    const float* Wout   = (const float*)d_in[26];
    const float* bout   = (const float*)d_in[27];
    float* out = (float*)d_out;

    float *xa, *CT, *R65p, *hbuf, *bb;
    __nv_bfloat16 *xmh, *w1h, *w2h, *wch, *wcl, *uh, *axh, *axl;
    cudaGetSymbolAddress((void**)&xa,    g_xa);
    cudaGetSymbolAddress((void**)&CT,    g_CT);
    cudaGetSymbolAddress((void**)&R65p,  g_R65p);
    cudaGetSymbolAddress((void**)&hbuf,  g_h);
    cudaGetSymbolAddress((void**)&bb,    g_bb);
    cudaGetSymbolAddress((void**)&xmh,   g_xmh);
    cudaGetSymbolAddress((void**)&w1h,   g_w1h);
    cudaGetSymbolAddress((void**)&w2h,   g_w2h);
    cudaGetSymbolAddress((void**)&wch,   g_wch);  cudaGetSymbolAddress((void**)&wcl, g_wcl);
    cudaGetSymbolAddress((void**)&uh,    g_uh);
    cudaGetSymbolAddress((void**)&axh,   g_axh);  cudaGetSymbolAddress((void**)&axl, g_axl);

    dim3 t32x8(32, 8);
    // weight prep
    prep_kernel<<<1, 1024>>>(reattn, rn_g, rn_b);
    wsplit_h_kernel<<<dim3(CC/32, DD/32), t32x8>>>(W1, w1h, DD, CC);
    wsplit_h_kernel<<<dim3(DD/32, C2/32), t32x8>>>(W2, w2h, C2, DD);
    wsum_kernel<<<dim3(DD/32, DD/32), t32x8>>>(Wout);
    wscale_kernel<<<dim3(DD/32, DD/32), t32x8>>>(Wout, ls2);
    wvt_kernel<<<dim3(DD/32, DD/32, 2), t32x8>>>(Wqkv);

    // LN + split of x into wide A cols 768..1535
    ln_x_kernel<<<ROWS, 256>>>(x, ln1_g, ln1_b, ln2_g, ln2_b);
    xsplit_kernel<<<dim3(3, ROWS), 256>>>(x);

    // attention path (exact fp32, constant over sequence)
    sgemm_part<<<dim3(6, KSEG, 4), 256>>>(CT, xa, R65p, NN, DD, DD, (size_t)NN*DD);
    r65red_kernel<<<(BB*128*DD)/256, 256>>>();
    vsum2_kernel<<<768, 256>>>(bqkv);
    attnvec_kernel<<<4, 768>>>(Wproj, bproj);
    bb_kernel<<<4, 768>>>(Wout, bout, ls1);

    // h = gelu(xm @ W1 + b1)   [pure bf16 — ls2-damped path]
    mma_gemm<<<dim3(CC/128, ROWS/128), 256>>>(
        xmh, nullptr, w1h, nullptr, DD, 1, hbuf, CC,
        nullptr, nullptr, 0, b1, nullptr, nullptr, 0, 1);
    ln_g_kernel<<<ROWS, 256>>>(gn_g, gn_b);
    conv_kernel<<<dim3(C2/64, ROWS/64), 256>>>(conv_w, conv_b);
    // m = u @ W2 + b2 -> bf16 split into wide A cols 0..767  [pure bf16]
    mma_gemm<<<dim3(DD/128, ROWS/128), 256>>>(
        uh, nullptr, w2h, nullptr, C2, 1, nullptr, 0,
        axh, axl, C2, b2, nullptr, nullptr, 0, 2);
    // out = [m|x] @ [Wb'|Ws]^T + x + bb[batch]   [3-term split: O(1) magnitudes]
    mma_gemm<<<dim3(DD/128, ROWS/128), 256>>>(
        axh, axl, wch, wcl, C2, 3, out, DD,
        nullptr, nullptr, 0, nullptr, bb, x, DD, 4);
}

// round 17
// speedup vs baseline: 1.4971x; 1.0252x over previous
#include <cuda_runtime.h>
#include <cuda_bf16.h>
#include <math.h>
#include <stdint.h>

#define BB 4
#define NN 1024
#define DD 768
#define HH 12
#define CC 3072
#define C2 1536
#define ROWS (BB*NN)
#define KSEG 8

// ---------------- fp32 scratch ----------------
__device__ float g_xa[ROWS*DD];
__device__ float g_CT[128*NN];
__device__ float g_csum[65];
__device__ float g_R65p[KSEG*BB*128*DD];
__device__ float g_R65[BB*128*DD];
__device__ float g_wvt[2*DD*DD];
__device__ float g_vsum[2*BB*DD];
__device__ float g_w[2*HH];
__device__ float g_attn[BB*DD];
__device__ float g_bb[BB*DD];

// ---------------- bf16 buffers ----------------
__device__ __align__(16) __nv_bfloat16 g_h[ROWS*CC];      // gelu output, bf16 (damped path)
__device__ __align__(16) __nv_bfloat16 g_xgln[ROWS*C2];   // LN(gate), bf16
__device__ __align__(16) __nv_bfloat16 g_xmh[ROWS*DD];
__device__ __align__(16) __nv_bfloat16 g_w1h[CC*DD];
__device__ __align__(16) __nv_bfloat16 g_w2h[DD*C2];
__device__ __align__(16) __nv_bfloat16 g_wch[DD*C2], g_wcl[DD*C2];   // [N=768,K=1536] = [Wb' | Ws]
__device__ __align__(16) __nv_bfloat16 g_uh[ROWS*C2];
__device__ __align__(16) __nv_bfloat16 g_axh[ROWS*C2], g_axl[ROWS*C2]; // [m | x]; lo used only for x-half

__device__ __forceinline__ float geluf(float v) {
    return 0.5f * v * (1.0f + erff(v * 0.7071067811865476f));
}
__device__ __forceinline__ void split_bf16(float v, __nv_bfloat16& h, __nv_bfloat16& l) {
    h = __float2bfloat16(v);
    l = __float2bfloat16(v - __bfloat162float(h));
}

// ================= mma.sync helpers ====
__device__ __forceinline__ void ldsm_x4(uint32_t& r0, uint32_t& r1, uint32_t& r2, uint32_t& r3, uint32_t a) {
    asm volatile("ldmatrix.sync.aligned.m8n8.x4.shared.b16 {%0,%1,%2,%3}, [%4];"
        : "=r"(r0), "=r"(r1), "=r"(r2), "=r"(r3) : "r"(a));
}
__device__ __forceinline__ void mma_bf16(float* d, const uint32_t* a, const uint32_t* b) {
    asm volatile("mma.sync.aligned.m16n8k16.row.col.f32.bf16.bf16.f32 "
        "{%0,%1,%2,%3}, {%4,%5,%6,%7}, {%8,%9}, {%0,%1,%2,%3};"
        : "+f"(d[0]), "+f"(d[1]), "+f"(d[2]), "+f"(d[3])
        : "r"(a[0]), "r"(a[1]), "r"(a[2]), "r"(a[3]), "r"(b[0]), "r"(b[1]));
}
__device__ __forceinline__ void cp16(uint32_t s, const void* g) {
    asm volatile("cp.async.cg.shared.global [%0], [%1], 16;" :: "r"(s), "l"(g));
}
#define CP_COMMIT() asm volatile("cp.async.commit_group;" ::: "memory")
#define CP_WAIT1()  asm volatile("cp.async.wait_group 1;" ::: "memory")

// ================= split-bf16 GEMM: D = A @ B^T =============
// A: [M,K] K-major bf16 hi/lo.  B: [N,K] K-major bf16 hi/lo.
// Tile 128x128, K chunk 32, 256 thr, static double-buffered cp.async.
// Phase 0 (Ah.Bh) covers ALL K chunks; phases 1 (Ah.Bl) and 2 (Al.Bh) cover
// only chunks >= splitStart (the region needing split-fp32 accuracy).
// splitStart == kSteps -> pure bf16.
// modes: 1: Cbh = bf16(gelu(v+bias))
//        2: Cbh = bf16(v+bias)           (hi only)
//        4: C = v + resid + bias2[(row>>10)*768 + col]   (f32)
#define SROW 40   // padded row stride in bf16 elems (80B: conflict-free ldmatrix)
__global__ __launch_bounds__(256) void mma_gemm(
    const __nv_bfloat16* __restrict__ Ah, const __nv_bfloat16* __restrict__ Al,
    const __nv_bfloat16* __restrict__ Bh, const __nv_bfloat16* __restrict__ Bl,
    int K, int splitStart,
    float* __restrict__ C, int ldc,
    __nv_bfloat16* __restrict__ Cbh, int ldcb,
    const float* __restrict__ bias, const float* __restrict__ bias2,
    const float* __restrict__ resid, int ldr, int mode)
{
    __shared__ __align__(16) __nv_bfloat16 sA[2][128*SROW];
    __shared__ __align__(16) __nv_bfloat16 sB[2][128*SROW];
    const int tid = threadIdx.x, lane = tid & 31, wid = tid >> 5;
    const int m0 = blockIdx.y * 128, n0 = blockIdx.x * 128;
    const int wm = wid >> 1, wn = wid & 1;            // 4x2 warp grid
    const int mb = wm * 32, nb = wn * 64;

    float acc[2][8][4];
    #pragma unroll
    for (int i = 0; i < 2; i++)
        #pragma unroll
        for (int j = 0; j < 8; j++)
            #pragma unroll
            for (int q = 0; q < 4; q++) acc[i][j][q] = 0.0f;

    const int kSteps = K >> 5;
    const int rem = kSteps - splitStart;
    const int nIter = kSteps + 2 * rem;
    const int lr = tid >> 2, lc = (tid & 3) * 8;      // cp.async mapping

    auto loadStage = [&](int iter, int st) {
        int ph, kc;
        if (iter < kSteps) { ph = 0; kc = iter; }
        else {
            int j = iter - kSteps;
            if (j < rem) { ph = 1; kc = splitStart + j; }
            else         { ph = 2; kc = splitStart + (j - rem); }
        }
        const __nv_bfloat16* A = (ph < 2) ? Ah : Al;
        const __nv_bfloat16* B = (ph == 1) ? Bl : Bh;
        int k0 = kc << 5;
        uint32_t sa = (uint32_t)__cvta_generic_to_shared(&sA[st][0]);
        uint32_t sb = (uint32_t)__cvta_generic_to_shared(&sB[st][0]);
        cp16(sa + (lr*SROW + lc)*2,        A + (size_t)(m0 + lr)      * K + k0 + lc);
        cp16(sa + ((lr+64)*SROW + lc)*2,   A + (size_t)(m0 + lr + 64) * K + k0 + lc);
        cp16(sb + (lr*SROW + lc)*2,        B + (size_t)(n0 + lr)      * K + k0 + lc);
        cp16(sb + ((lr+64)*SROW + lc)*2,   B + (size_t)(n0 + lr + 64) * K + k0 + lc);
    };

    loadStage(0, 0);
    CP_COMMIT();
    for (int i = 0; i < nIter; i++) {
        if (i + 1 < nIter) loadStage(i + 1, (i + 1) & 1);
        CP_COMMIT();
        CP_WAIT1();
        __syncthreads();
        int st = i & 1;
        uint32_t sa = (uint32_t)__cvta_generic_to_shared(&sA[st][0]);
        uint32_t sb = (uint32_t)__cvta_generic_to_shared(&sB[st][0]);
        #pragma unroll
        for (int ks = 0; ks < 2; ks++) {
            int kl = ks * 16;
            uint32_t af[2][4];
            #pragma unroll
            for (int mt = 0; mt < 2; mt++) {
                int row = mb + mt*16 + (lane & 15);
                int ko  = kl + ((lane >> 4) << 3);
                ldsm_x4(af[mt][0], af[mt][1], af[mt][2], af[mt][3],
                        sa + (uint32_t)(row*SROW + ko)*2);
            }
            uint32_t bf[8][2];
            #pragma unroll
            for (int nt4 = 0; nt4 < 4; nt4++) {
                int nrow = nb + nt4*16 + (lane & 7) + ((lane >> 4) << 3);
                int ko   = kl + (((lane >> 3) & 1) << 3);
                uint32_t r0, r1, r2, r3;
                ldsm_x4(r0, r1, r2, r3, sb + (uint32_t)(nrow*SROW + ko)*2);
                bf[nt4*2][0] = r0; bf[nt4*2][1] = r1;
                bf[nt4*2+1][0] = r2; bf[nt4*2+1][1] = r3;
            }
            #pragma unroll
            for (int mt = 0; mt < 2; mt++)
                #pragma unroll
                for (int nt = 0; nt < 8; nt++)
                    mma_bf16(acc[mt][nt], af[mt], bf[nt]);
        }
        __syncthreads();
    }

    // epilogue
    #pragma unroll
    for (int mt = 0; mt < 2; mt++) {
        #pragma unroll
        for (int nt = 0; nt < 8; nt++) {
            int row = m0 + mb + mt*16 + (lane >> 2);
            int col = n0 + nb + nt*8 + (lane & 3)*2;
            #pragma unroll
            for (int h = 0; h < 2; h++) {
                int rr = row + h*8;
                #pragma unroll
                for (int q = 0; q < 2; q++) {
                    int cc = col + q;
                    float v = acc[mt][nt][h*2 + q];
                    if (mode == 1) {
                        Cbh[(size_t)rr*ldcb + cc] = __float2bfloat16(geluf(v + bias[cc]));
                    } else if (mode == 2) {
                        Cbh[(size_t)rr*ldcb + cc] = __float2bfloat16(v + bias[cc]);
                    } else {
                        C[(size_t)rr*ldc + cc] = v + resid[(size_t)rr*ldr + cc]
                                               + bias2[(size_t)(rr >> 10)*DD + cc];
                    }
                }
            }
        }
    }
}

// ================= weight prep =================
// hi-only transpose: W[K,N] f32 -> Wh[N,K] bf16
__global__ void wsplit_h_kernel(const float* __restrict__ W,
                                __nv_bfloat16* __restrict__ Wh, int K, int N) {
    __shared__ float t[32][33];
    int n0 = blockIdx.x * 32, k0 = blockIdx.y * 32;
    int tx = threadIdx.x, ty = threadIdx.y;
    for (int i = ty; i < 32; i += 8) t[i][tx] = W[(size_t)(k0 + i) * N + n0 + tx];
    __syncthreads();
    for (int i = ty; i < 32; i += 8)
        Wh[(size_t)(n0 + i) * K + k0 + tx] = __float2bfloat16(t[tx][i]);
}

// Ws = Wout[0:768]+Wout[768:1536] -> cols 768..1535 of concat B (hi+lo)
__global__ void wsum_kernel(const float* __restrict__ Wout) {
    __shared__ float t[32][33];
    int n0 = blockIdx.x * 32, k0 = blockIdx.y * 32;
    int tx = threadIdx.x, ty = threadIdx.y;
    for (int i = ty; i < 32; i += 8)
        t[i][tx] = Wout[(size_t)(k0 + i) * DD + n0 + tx]
                 + Wout[(size_t)(DD + k0 + i) * DD + n0 + tx];
    __syncthreads();
    for (int i = ty; i < 32; i += 8) {
        float v = t[tx][i];
        __nv_bfloat16 h, l; split_bf16(v, h, l);
        g_wch[(size_t)(n0 + i) * C2 + DD + k0 + tx] = h;
        g_wcl[(size_t)(n0 + i) * C2 + DD + k0 + tx] = l;
    }
}

// Wb' = diag(ls2)*Wout[768:1536] -> cols 0..767 of concat B (hi only; lo never read)
__global__ void wscale_kernel(const float* __restrict__ Wout, const float* __restrict__ ls2) {
    __shared__ float t[32][33];
    int n0 = blockIdx.x * 32, k0 = blockIdx.y * 32;
    int tx = threadIdx.x, ty = threadIdx.y;
    for (int i = ty; i < 32; i += 8)
        t[i][tx] = ls2[k0 + i] * Wout[(size_t)(DD + k0 + i) * DD + n0 + tx];
    __syncthreads();
    for (int i = ty; i < 32; i += 8)
        g_wch[(size_t)(n0 + i) * C2 + k0 + tx] = __float2bfloat16(t[tx][i]);
}

__global__ void wvt_kernel(const float* __restrict__ Wqkv) {
    __shared__ float t[32][33];
    int p = blockIdx.z;
    const float* W = Wqkv + (size_t)p * DD * (3*DD) + 2*DD;
    int j0 = blockIdx.x * 32, k0 = blockIdx.y * 32;
    int tx = threadIdx.x, ty = threadIdx.y;
    for (int i = ty; i < 32; i += 8) t[i][tx] = W[(size_t)(k0 + i) * (3*DD) + j0 + tx];
    __syncthreads();
    for (int i = ty; i < 32; i += 8)
        g_wvt[(size_t)p * DD * DD + (size_t)(j0 + i) * DD + k0 + tx] = t[tx][i];
}

// ---------------- prep: rope coef table + reattn weights ----------------
__global__ void prep_kernel(const float* __restrict__ reattn,
                            const float* __restrict__ rng,
                            const float* __restrict__ rnb) {
    __shared__ float smix[24];
    int tid = threadIdx.x;
    float fi = (float)tid;
    float power = (fi - 512.0f) / 512.0f;
    #pragma unroll
    for (int t = 0; t < 16; t++) {
        float inv = powf(10000.0f, -(float)t / 16.0f);
        float fr = fi * inv;
        float c = cosf(fr), s = sinf(fr);
        int u1 = (2*t) & 15, u2 = (2*t+1) & 15;
        float sA = powf((2.0f*u1 + 12.8f) / 44.8f, -power);
        float sB = powf((2.0f*u2 + 12.8f) / 44.8f, -power);
        g_CT[(4*t+0)*NN + tid] = sA * c;
        g_CT[(4*t+1)*NN + tid] = sA * s;
        g_CT[(4*t+2)*NN + tid] = sB * c;
        g_CT[(4*t+3)*NN + tid] = sB * s;
    }
    g_CT[64*NN + tid] = 1.0f;
    __syncthreads();
    int warp = tid >> 5, lane = tid & 31;
    for (int c = warp; c < 65; c += 32) {
        float s = 0.0f;
        for (int q = lane; q < NN; q += 32) s += g_CT[c*NN + q];
        #pragma unroll
        for (int o = 16; o; o >>= 1) s += __shfl_down_sync(0xffffffffu, s, o);
        if (lane == 0) g_csum[c] = s;
    }
    if (tid < 24) {
        int p = tid / 12, g = tid % 12;
        float m = 0.0f;
        for (int h = 0; h < 12; h++) m += reattn[p*144 + h*12 + g];
        smix[tid] = m;
    }
    __syncthreads();
    if (tid < 24) {
        int p = tid / 12;
        float mean = 0.0f, var = 0.0f;
        for (int g = 0; g < 12; g++) mean += smix[p*12+g];
        mean *= (1.0f/12.0f);
        for (int g = 0; g < 12; g++) { float d = smix[p*12+g]-mean; var += d*d; }
        var *= (1.0f/12.0f);
        float rs = rsqrtf(var + 1e-5f);
        g_w[tid] = (smix[tid]-mean)*rs*rng[tid] + rnb[tid];
    }
}

// ---------------- LN of x -> xa (f32), xm (bf16), AND x split -> wide A cols 768+ ----------------
__global__ void ln_x_kernel(const float* __restrict__ x,
                            const float* __restrict__ g1, const float* __restrict__ b1,
                            const float* __restrict__ g2, const float* __restrict__ b2) {
    __shared__ float sh1[33], sh2[33];
    int row = blockIdx.x, tid = threadIdx.x;
    const float* xr = x + (size_t)row * DD;
    float s = 0.0f, s2 = 0.0f;
    #pragma unroll
    for (int c = tid; c < DD; c += 256) { float v = xr[c]; s += v; s2 += v*v; }
    int lane = tid & 31, warp = tid >> 5;
    #pragma unroll
    for (int o = 16; o; o >>= 1) { s += __shfl_down_sync(~0u, s, o); s2 += __shfl_down_sync(~0u, s2, o); }
    if (lane == 0) { sh1[warp] = s; sh2[warp] = s2; }
    __syncthreads();
    if (warp == 0) {
        s  = (lane < 8) ? sh1[lane] : 0.0f;
        s2 = (lane < 8) ? sh2[lane] : 0.0f;
        #pragma unroll
        for (int o = 4; o; o >>= 1) { s += __shfl_down_sync(~0u, s, o); s2 += __shfl_down_sync(~0u, s2, o); }
        if (lane == 0) { sh1[32] = s; sh2[32] = s2; }
    }
    __syncthreads();
    float mean = sh1[32] * (1.0f/DD);
    float var  = sh2[32] * (1.0f/DD) - mean*mean;
    float rs = rsqrtf(var + 1e-5f);
    #pragma unroll
    for (int c = tid; c < DD; c += 256) {
        float raw = xr[c];
        float v = (raw - mean) * rs;
        g_xa[(size_t)row*DD + c] = v * g1[c] + b1[c];
        g_xmh[(size_t)row*DD + c] = __float2bfloat16(v * g2[c] + b2[c]);
        __nv_bfloat16 h, l; split_bf16(raw, h, l);
        g_axh[(size_t)row*C2 + DD + c] = h;
        g_axl[(size_t)row*C2 + DD + c] = l;
    }
}

// ---------------- LN of gate half of h (bf16 in, bf16 out) ----------------
__global__ void ln_g_kernel(const float* __restrict__ gg, const float* __restrict__ gb) {
    __shared__ float sh1[33], sh2[33];
    int row = blockIdx.x, tid = threadIdx.x;
    const __nv_bfloat16* xr = g_h + (size_t)row * CC + C2;
    float s = 0.0f, s2 = 0.0f;
    #pragma unroll
    for (int c = tid; c < C2; c += 256) { float v = __bfloat162float(xr[c]); s += v; s2 += v*v; }
    int lane = tid & 31, warp = tid >> 5;
    #pragma unroll
    for (int o = 16; o; o >>= 1) { s += __shfl_down_sync(~0u, s, o); s2 += __shfl_down_sync(~0u, s2, o); }
    if (lane == 0) { sh1[warp] = s; sh2[warp] = s2; }
    __syncthreads();
    if (warp == 0) {
        s  = (lane < 8) ? sh1[lane] : 0.0f;
        s2 = (lane < 8) ? sh2[lane] : 0.0f;
        #pragma unroll
        for (int o = 4; o; o >>= 1) { s += __shfl_down_sync(~0u, s, o); s2 += __shfl_down_sync(~0u, s2, o); }
        if (lane == 0) { sh1[32] = s; sh2[32] = s2; }
    }
    __syncthreads();
    float mean = sh1[32] * (1.0f/C2);
    float var  = sh2[32] * (1.0f/C2) - mean*mean;
    float rs = rsqrtf(var + 1e-5f);
    #pragma unroll
    for (int c = tid; c < C2; c += 256) {
        float v = (__bfloat162float(xr[c]) - mean) * rs;
        g_xgln[(size_t)row*C2 + c] = __float2bfloat16(v * gg[c] + gb[c]);
    }
}

// ---------------- fp32 SGEMM, K-split into 8 segments (R65 reduction) ----------------
__global__ __launch_bounds__(256) void sgemm_part(
    const float* __restrict__ A, const float* __restrict__ B, float* __restrict__ Cp,
    int K, int ldb, int ldc, size_t bStride)
{
    __shared__ float As[8][128];
    __shared__ float Bs[8][128];
    int seg = blockIdx.y, bz = blockIdx.z;
    B += (size_t)bz * bStride;
    float* C = Cp + (size_t)seg * (BB*128*DD) + (size_t)bz * (128*DD);
    int kbase = seg * (K / KSEG);
    int tid = threadIdx.x;
    int n0 = blockIdx.x * 128;
    int aRow = tid >> 1, aCol = (tid & 1) * 4;
    int bRow = tid >> 5, bCol = (tid & 31) * 4;
    const float* Ag = A + (size_t)aRow * K + kbase + aCol;
    const float* Bg = B + (size_t)(kbase + bRow) * ldb + n0 + bCol;
    float acc[8][8];
    #pragma unroll
    for (int i = 0; i < 8; i++)
        #pragma unroll
        for (int j = 0; j < 8; j++) acc[i][j] = 0.0f;
    int ty = tid >> 4, tx = tid & 15;
    for (int k0 = 0; k0 < K / KSEG; k0 += 8) {
        float4 av = *(const float4*)(Ag + k0);
        As[aCol+0][aRow] = av.x; As[aCol+1][aRow] = av.y;
        As[aCol+2][aRow] = av.z; As[aCol+3][aRow] = av.w;
        float4 bv = *(const float4*)(Bg + (size_t)k0 * ldb);
        *(float4*)&Bs[bRow][bCol] = bv;
        __syncthreads();
        #pragma unroll
        for (int kk = 0; kk < 8; kk++) {
            float a[8], b[8];
            *(float4*)(a)   = *(const float4*)&As[kk][ty*8];
            *(float4*)(a+4) = *(const float4*)&As[kk][ty*8+4];
            *(float4*)(b)   = *(const float4*)&Bs[kk][tx*8];
            *(float4*)(b+4) = *(const float4*)&Bs[kk][tx*8+4];
            #pragma unroll
            for (int i = 0; i < 8; i++)
                #pragma unroll
                for (int j = 0; j < 8; j++)
                    acc[i][j] += a[i] * b[j];
        }
        __syncthreads();
    }
    #pragma unroll
    for (int i = 0; i < 8; i++) {
        int r = ty*8 + i;
        #pragma unroll
        for (int j = 0; j < 8; j++)
            C[(size_t)r*ldc + n0 + tx*8 + j] = acc[i][j];
    }
}

__global__ void r65red_kernel() {
    int idx = blockIdx.x * 256 + threadIdx.x;   // BB*128*DD total
    float s = 0.0f;
    #pragma unroll
    for (int seg = 0; seg < KSEG; seg++)
        s += g_R65p[(size_t)seg * (BB*128*DD) + idx];
    g_R65[idx] = s;
}

// ---------------- vsum: warp-per-output using transposed Wv ----------------
__global__ void vsum2_kernel(const float* __restrict__ bqkv) {
    int gw = (blockIdx.x * blockDim.x + threadIdx.x) >> 5;
    int lane = threadIdx.x & 31;
    int j = gw % DD;
    int b = (gw / DD) & 3;
    int p = gw / (4 * DD);
    const float* bv = bqkv + p * (3*DD) + 2*DD;
    const float* R  = g_R65 + (size_t)b * 128 * DD;
    const float* Wt = g_wvt + (size_t)p * DD * DD;
    int c = j & 63;
    float acc = 0.0f;
    if (c < 32) {
        int t = c >> 1;
        int r1, r2, j2; float sgn;
        if (!(c & 1)) { r1 = 4*t;   r2 = 4*t+1; j2 = j+1; sgn = -1.0f; }
        else          { r1 = 4*t+2; r2 = 4*t+3; j2 = j-1; sgn =  1.0f; }
        const float* R1 = R + (size_t)r1 * DD;
        const float* R2 = R + (size_t)r2 * DD;
        const float* Wa = Wt + (size_t)j  * DD;
        const float* Wb = Wt + (size_t)j2 * DD;
        float a1 = 0.0f, a2 = 0.0f;
        for (int k = lane; k < DD; k += 32) { a1 += Wa[k]*R1[k]; a2 += Wb[k]*R2[k]; }
        acc = a1 + sgn * a2;
        #pragma unroll
        for (int o = 16; o; o >>= 1) acc += __shfl_down_sync(~0u, acc, o);
        if (lane == 0) acc += bv[j]*g_csum[r1] + sgn*bv[j2]*g_csum[r2];
    } else {
        const float* Rr = R + (size_t)64 * DD;
        const float* Wa = Wt + (size_t)j * DD;
        float a = 0.0f;
        for (int k = lane; k < DD; k += 32) a += Wa[k]*Rr[k];
        #pragma unroll
        for (int o = 16; o; o >>= 1) a += __shfl_down_sync(~0u, a, o);
        if (lane == 0) acc = a + bv[j]*g_csum[64];
    }
    if (lane == 0) g_vsum[((size_t)p*BB + b)*DD + j] = acc;
}

// ---------------- attn vector (constant over sequence) ----------------
__global__ void attnvec_kernel(const float* __restrict__ Wproj, const float* __restrict__ bproj) {
    __shared__ float yv[2*DD];
    int b = blockIdx.x, tid = threadIdx.x;
    #pragma unroll
    for (int p = 0; p < 2; p++)
        yv[p*DD + tid] = g_w[p*HH + (tid >> 6)] * g_vsum[((size_t)p*BB + b)*DD + tid];
    __syncthreads();
    float acc = 0.0f;
    #pragma unroll
    for (int p = 0; p < 2; p++) {
        acc += bproj[p*DD + tid];
        const float* Wp = Wproj + (size_t)p * DD * DD;
        const float* y = yv + p*DD;
        for (int jj = 0; jj < DD; jj++)
            acc += y[jj] * Wp[(size_t)jj*DD + tid];
    }
    g_attn[(size_t)b*DD + tid] = acc;
}

// ---------------- bb[b][c] = bout[c] + sum_k ls1[k]*attn[b][k]*Wout[k][c] ----------------
__global__ void bb_kernel(const float* __restrict__ Wout, const float* __restrict__ bout,
                          const float* __restrict__ ls1) {
    __shared__ float cv[DD];
    int b = blockIdx.x, c = threadIdx.x;
    cv[c] = ls1[c] * g_attn[(size_t)b*DD + c];
    __syncthreads();
    float acc = bout[c];
    for (int k = 0; k < DD; k++)
        acc += cv[k] * Wout[(size_t)k*DD + c];
    g_bb[(size_t)b*DD + c] = acc;
}

// ---------------- tiled depthwise conv (K=21) + gate -> u bf16 ----------------
__global__ __launch_bounds__(256) void conv_kernel(const float* __restrict__ cw,
                                                   const float* __restrict__ cb) {
    __shared__ float sx[84*64];
    __shared__ float scw[64*21];
    int ch0 = blockIdx.x * 64;
    int r0  = blockIdx.y * 64;
    int tid = threadIdx.x;
    for (int q = tid; q < 64*21; q += 256) {
        int ch = q / 21, k = q % 21;
        scw[ch*21 + k] = cw[(size_t)(ch0 + ch)*21 + k];
    }
    int b = r0 >> 10, i0 = r0 & 1023;
    for (int q = tid; q < 84*64; q += 256) {
        int rr = q >> 6, ch = q & 63;
        int ii = i0 - 10 + rr;
        sx[rr*64 + ch] = (ii >= 0 && ii < NN)
            ? __bfloat162float(g_xgln[((size_t)((b << 10) + ii))*C2 + ch0 + ch]) : 0.0f;
    }
    __syncthreads();
    int ch = tid & 63, ty = tid >> 6;
    float cbv = cb[ch0 + ch];
    float w[21];
    #pragma unroll
    for (int k = 0; k < 21; k++) w[k] = scw[ch*21 + k];
    for (int rg = 0; rg < 16; rg++) {
        int r = ty*16 + rg;
        float acc = cbv;
        #pragma unroll
        for (int k = 0; k < 21; k++)
            acc += w[k] * sx[(r + k)*64 + ch];
        int row = r0 + r;
        float v = __bfloat162float(g_h[(size_t)row*CC + ch0 + ch]) * acc;
        g_uh[(size_t)row*C2 + ch0 + ch] = __float2bfloat16(v);
    }
}

// ---------------- launch ----------------
extern "C" void kernel_launch(void* const* d_in, const int* in_sizes, int n_in,
                              void* d_out, int out_size) {
    const float* x      = (const float*)d_in[0];
    const float* Wqkv   = (const float*)d_in[1];
    const float* bqkv   = (const float*)d_in[2];
    const float* Wproj  = (const float*)d_in[3];
    const float* bproj  = (const float*)d_in[4];
    const float* reattn = (const float*)d_in[9];
    const float* rn_g   = (const float*)d_in[10];
    const float* rn_b   = (const float*)d_in[11];
    const float* ln1_g  = (const float*)d_in[12];
    const float* ln1_b  = (const float*)d_in[13];
    const float* ln2_g  = (const float*)d_in[14];
    const float* ln2_b  = (const float*)d_in[15];
    const float* ls1    = (const float*)d_in[16];
    const float* ls2    = (const float*)d_in[17];
    const float* W1     = (const float*)d_in[18];
    const float* b1     = (const float*)d_in[19];
    const float* gn_g   = (const float*)d_in[20];
    const float* gn_b   = (const float*)d_in[21];
    const float* conv_w = (const float*)d_in[22];
    const float* conv_b = (const float*)d_in[23];
    const float* W2     = (const float*)d_in[24];
    const float* b2     = (const float*)d_in[25];
    const float* Wout   = (const float*)d_in[26];
    const float* bout   = (const float*)d_in[27];
    float* out = (float*)d_out;

    float *xa, *CT, *R65p, *bb;
    __nv_bfloat16 *hbuf, *xmh, *w1h, *w2h, *wch, *wcl, *uh, *axh, *axl;
    cudaGetSymbolAddress((void**)&xa,    g_xa);
    cudaGetSymbolAddress((void**)&CT,    g_CT);
    cudaGetSymbolAddress((void**)&R65p,  g_R65p);
    cudaGetSymbolAddress((void**)&bb,    g_bb);
    cudaGetSymbolAddress((void**)&hbuf,  g_h);
    cudaGetSymbolAddress((void**)&xmh,   g_xmh);
    cudaGetSymbolAddress((void**)&w1h,   g_w1h);
    cudaGetSymbolAddress((void**)&w2h,   g_w2h);
    cudaGetSymbolAddress((void**)&wch,   g_wch);  cudaGetSymbolAddress((void**)&wcl, g_wcl);
    cudaGetSymbolAddress((void**)&uh,    g_uh);
    cudaGetSymbolAddress((void**)&axh,   g_axh);  cudaGetSymbolAddress((void**)&axl, g_axl);

    dim3 t32x8(32, 8);
    // weight prep
    prep_kernel<<<1, 1024>>>(reattn, rn_g, rn_b);
    wsplit_h_kernel<<<dim3(CC/32, DD/32), t32x8>>>(W1, w1h, DD, CC);
    wsplit_h_kernel<<<dim3(DD/32, C2/32), t32x8>>>(W2, w2h, C2, DD);
    wsum_kernel<<<dim3(DD/32, DD/32), t32x8>>>(Wout);
    wscale_kernel<<<dim3(DD/32, DD/32), t32x8>>>(Wout, ls2);
    wvt_kernel<<<dim3(DD/32, DD/32, 2), t32x8>>>(Wqkv);

    // LN(x) + xm bf16 + x split into wide A cols 768..1535 (fused)
    ln_x_kernel<<<ROWS, 256>>>(x, ln1_g, ln1_b, ln2_g, ln2_b);

    // attention path (exact fp32, constant over sequence)
    sgemm_part<<<dim3(6, KSEG, 4), 256>>>(CT, xa, R65p, NN, DD, DD, (size_t)NN*DD);
    r65red_kernel<<<(BB*128*DD)/256, 256>>>();
    vsum2_kernel<<<768, 256>>>(bqkv);
    attnvec_kernel<<<4, 768>>>(Wproj, bproj);
    bb_kernel<<<4, 768>>>(Wout, bout, ls1);

    // h = gelu(xm @ W1 + b1) -> bf16   [pure bf16, damped path]
    mma_gemm<<<dim3(CC/128, ROWS/128), 256>>>(
        xmh, nullptr, w1h, nullptr, DD, DD/32, nullptr, 0,
        hbuf, CC, b1, nullptr, nullptr, 0, 1);
    ln_g_kernel<<<ROWS, 256>>>(gn_g, gn_b);
    conv_kernel<<<dim3(C2/64, ROWS/64), 256>>>(conv_w, conv_b);
    // m = u @ W2 + b2 -> bf16 (hi only) into wide A cols 0..767  [pure bf16]
    mma_gemm<<<dim3(DD/128, ROWS/128), 256>>>(
        uh, nullptr, w2h, nullptr, C2, C2/32, nullptr, 0,
        axh, C2, b2, nullptr, nullptr, 0, 2);
    // out = [m|x] @ [Wb'|Ws]^T + x + bb[batch]
    // phases 1,2 only over x-half chunks (splitStart = 768/32 = 24)
    mma_gemm<<<dim3(DD/128, ROWS/128), 256>>>(
        axh, axl, wch, wcl, C2, DD/32, out, DD,
        nullptr, 0, nullptr, bb, x, DD, 4);
}